// round 5
// baseline (speedup 1.0000x reference)
#include <cuda_runtime.h>
#include <cuda_bf16.h>

// Problem constants
#define BB   64
#define SS   1024
#define II   512
#define HH   512
#define NG3  1536          // 3*H
#define STEPN 4608         // [Wh1 | Wi2 | Wh2] columns
#define NCTA  144          // persistent CTAs (1/SM guaranteed by smem)
#define ASTR  516          // A smem stride words; 516%32==4 -> conflict-free A frags
#define BSTR  40           // B smem stride words; 40%32==8 -> conflict-free B frags
#define SCAN_SMEM ((64 * ASTR + 512 * BSTR) * 4)   // 214016 B
#define EWTOT (2 * BB * HH)                        // 65536 elementwise items
#define NTHR  (NCTA * 128)
#define ESLOT 4

// ---------------- static device scratch --------------------------------------
__device__ float g_xs1[(long)SS * BB * NG3];   // layer-1 input projections [s][b][3H]
__device__ float g_G[BB * STEPN];              // per-step GEMM results
__device__ float g_h[2][2][BB * HH];           // fp32 h   [pingpong][layer][b*H]
__device__ float g_ha[2][2][BB * HH];          // tf32-rounded h (A operand copy)
__device__ float g_gb1[BB * NG3];
__device__ float g_gb2[BB * NG3];
__device__ float g_h1b[BB * HH];
__device__ float g_fcin[BB * 2 * HH];          // [b][fwd H | bwd H]

__device__ unsigned g_flag[NCTA];              // per-CTA barrier arrival counters
__device__ unsigned g_gen = 0;                 // barrier generation (release word)

// ---------------- helpers ----------------------------------------------------
__device__ __forceinline__ unsigned f2tf(float f) {
    unsigned u;
    asm("cvt.rna.tf32.f32 %0, %1;" : "=r"(u) : "f"(f));
    return u;
}

__device__ __forceinline__ void mma8(float c[4], const unsigned a[4], unsigned b0, unsigned b1) {
    asm volatile(
        "mma.sync.aligned.m16n8k8.row.col.f32.tf32.tf32.f32 "
        "{%0,%1,%2,%3},{%4,%5,%6,%7},{%8,%9},{%0,%1,%2,%3};"
        : "+f"(c[0]), "+f"(c[1]), "+f"(c[2]), "+f"(c[3])
        : "r"(a[0]), "r"(a[1]), "r"(a[2]), "r"(a[3]), "r"(b0), "r"(b1));
}

__device__ __forceinline__ float sigm(float v) { return 1.f / (1.f + __expf(-v)); }
__device__ __forceinline__ float tanh_fast(float v) {
    return 1.f - 2.f / (1.f + __expf(2.f * v));
}

__device__ __forceinline__ void cpasync16(unsigned saddr, const void* g) {
    asm volatile("cp.async.cg.shared.global [%0], [%1], 16;" :: "r"(saddr), "l"(g));
}
__device__ __forceinline__ void cpasync_commit() {
    asm volatile("cp.async.commit_group;" ::: "memory");
}
template<int N>
__device__ __forceinline__ void cpasync_wait() {
    asm volatile("cp.async.wait_group %0;" :: "n"(N) : "memory");
}

// flag-array grid barrier: per-CTA release flag, CTA0/warp0 polls, releases gen.
// target must be the same monotonically increasing value in every CTA.
__device__ __forceinline__ void grid_bar(unsigned target, int ct) {
    __syncthreads();
    if (threadIdx.x < 32) {
        if (threadIdx.x == 0) {
            __threadfence();   // cumulative: publishes CTA's prior global writes
            asm volatile("st.release.gpu.u32 [%0], %1;"
                         :: "l"(&g_flag[ct]), "r"(target) : "memory");
        }
        if (ct == 0) {
            // CTA0 warp0: poll all arrival flags in parallel
            bool done = false;
            while (!done) {
                bool ok = true;
                for (int i = threadIdx.x; i < NCTA; i += 32) {
                    unsigned v;
                    asm volatile("ld.acquire.gpu.u32 %0, [%1];"
                                 : "=r"(v) : "l"(&g_flag[i]) : "memory");
                    if (v < target) ok = false;
                }
                done = __all_sync(0xFFFFFFFFu, ok);
            }
            if (threadIdx.x == 0)
                asm volatile("st.release.gpu.u32 [%0], %1;"
                             :: "l"(&g_gen), "r"(target) : "memory");
        } else if (threadIdx.x == 0) {
            unsigned cur;
            do {
                asm volatile("ld.acquire.gpu.u32 %0, [%1];"
                             : "=r"(cur) : "l"(&g_gen) : "memory");
            } while (cur < target);
        }
    }
    __syncthreads();
}

// ---------------- 64x64 TF32 GEMM core (non-scan kernels) --------------------
__device__ __forceinline__ void gemm_core(const float* __restrict__ A, long lda,
                                          const float* __restrict__ B512, int K,
                                          const float* __restrict__ bias,
                                          float* __restrict__ C, int ldc)
{
    __shared__ unsigned As[64][33];
    __shared__ unsigned Bs[32][65];

    const int tid  = threadIdx.x;
    const int lane = tid & 31;
    const int warp = tid >> 5;
    const int wm = warp >> 1, wn = warp & 1;
    const int g = lane >> 2, t = lane & 3;

    float acc[2][4][4];
#pragma unroll
    for (int a = 0; a < 2; a++)
#pragma unroll
        for (int b = 0; b < 4; b++)
#pragma unroll
            for (int c = 0; c < 4; c++) acc[a][b][c] = 0.f;

    float4 ra[4], rbv[4];
#pragma unroll
    for (int i = 0; i < 4; i++) {
        int f = tid + i * 128;
        ra[i]  = *(const float4*)(A + (long)(f >> 3) * lda + ((f & 7) << 2));
        rbv[i] = *(const float4*)(B512 + (long)(f >> 4) * 512 + ((f & 15) << 2));
    }

    for (int kc = 0; kc < K; kc += 32) {
#pragma unroll
        for (int i = 0; i < 4; i++) {
            int f = tid + i * 128;
            int r = f >> 3, cc = (f & 7) << 2;
            As[r][cc + 0] = f2tf(ra[i].x);
            As[r][cc + 1] = f2tf(ra[i].y);
            As[r][cc + 2] = f2tf(ra[i].z);
            As[r][cc + 3] = f2tf(ra[i].w);
            int bk = f >> 4, bc = (f & 15) << 2;
            Bs[bk][bc + 0] = f2tf(rbv[i].x);
            Bs[bk][bc + 1] = f2tf(rbv[i].y);
            Bs[bk][bc + 2] = f2tf(rbv[i].z);
            Bs[bk][bc + 3] = f2tf(rbv[i].w);
        }
        __syncthreads();

        if (kc + 32 < K) {
#pragma unroll
            for (int i = 0; i < 4; i++) {
                int f = tid + i * 128;
                ra[i]  = *(const float4*)(A + (long)(f >> 3) * lda + (kc + 32) + ((f & 7) << 2));
                rbv[i] = *(const float4*)(B512 + (long)(kc + 32 + (f >> 4)) * 512 + ((f & 15) << 2));
            }
        }

#pragma unroll
        for (int ks = 0; ks < 4; ks++) {
            int kb = ks * 8;
            unsigned afr[2][4];
#pragma unroll
            for (int mf = 0; mf < 2; mf++) {
                int rb_ = wm * 32 + mf * 16;
                afr[mf][0] = As[rb_ + g][kb + t];
                afr[mf][1] = As[rb_ + 8 + g][kb + t];
                afr[mf][2] = As[rb_ + g][kb + 4 + t];
                afr[mf][3] = As[rb_ + 8 + g][kb + 4 + t];
            }
#pragma unroll
            for (int nf = 0; nf < 4; nf++) {
                int cb = wn * 32 + nf * 8;
                unsigned b0 = Bs[kb + t][cb + g];
                unsigned b1 = Bs[kb + 4 + t][cb + g];
                mma8(acc[0][nf], afr[0], b0, b1);
                mma8(acc[1][nf], afr[1], b0, b1);
            }
        }
        __syncthreads();
    }

#pragma unroll
    for (int mf = 0; mf < 2; mf++)
#pragma unroll
        for (int nf = 0; nf < 4; nf++) {
            int row = wm * 32 + mf * 16 + g;
            int col = wn * 32 + nf * 8 + t * 2;
            float b0v = bias ? bias[col] : 0.f;
            float b1v = bias ? bias[col + 1] : 0.f;
            C[(long)row * ldc + col]           = acc[mf][nf][0] + b0v;
            C[(long)row * ldc + col + 1]       = acc[mf][nf][1] + b1v;
            C[(long)(row + 8) * ldc + col]     = acc[mf][nf][2] + b0v;
            C[(long)(row + 8) * ldc + col + 1] = acc[mf][nf][3] + b1v;
        }
}

// ---------------- kernels -----------------------------------------------------

__global__ void k_zero() {
    long n = 2L * 2 * BB * HH;
    float* p = &g_h[0][0][0];
    float* q = &g_ha[0][0][0];
    for (long i = blockIdx.x * blockDim.x + threadIdx.x; i < n; i += (long)gridDim.x * blockDim.x) {
        p[i] = 0.f;
        q[i] = 0.f;
    }
    if (blockIdx.x == 0 && threadIdx.x < NCTA) g_flag[threadIdx.x] = 0;
    if (blockIdx.x == 0 && threadIdx.x == 0) g_gen = 0;
}

// xs1[s][b][n] = x[b][s][:] @ Wi[0][0][gate] + b[0][0]
__global__ __launch_bounds__(128) void k_proj(const float* __restrict__ x,
                                              const float* __restrict__ Wi,
                                              const float* __restrict__ bv)
{
    int n = blockIdx.x * 64;
    int s = blockIdx.y;
    int gate = n >> 9, cig = n & 511;
    const float* A = x + (long)s * II;
    const float* B512 = Wi + ((long)(0 * 3 + gate)) * 512 * 512 + cig;   // Wi[0][0]
    gemm_core(A, (long)SS * II, B512, 512, bv + n,
              g_xs1 + ((long)s * BB) * NG3 + n, NG3);
}

// ---------------- persistent scan kernel --------------------------------------
// 144 CTAs x 128 threads; each CTA owns a 64x32 tile of the fused step GEMM.
// cols [0,1536)=h1@Wh1 ; [1536,3072)=h1@Wi2 ; [3072,4608)=h2@Wh2
__global__ void __launch_bounds__(128, 1) k_scan(const float* __restrict__ Wi,
                                                 const float* __restrict__ Wh,
                                                 const float* __restrict__ bv)
{
    extern __shared__ unsigned smemu[];
    unsigned* As = smemu;                 // 64 x ASTR
    unsigned* Bs = smemu + 64 * ASTR;     // 512 x BSTR

    const int tid  = threadIdx.x;
    const int lane = tid & 31;
    const int warp = tid >> 5;
    const int wm = warp >> 1, wn = warp & 1;
    const int gq = lane >> 2, tq = lane & 3;
    const int ct = blockIdx.x;
    const int seg = ct / 48;
    const int c0  = (ct * 32) % NG3;
    const int gate = c0 >> 9, cig = c0 & 511;

    const float* Wsrc;
    if (seg == 0)      Wsrc = Wh + (long)gate * 262144 + cig;        // Wh[0][0]
    else if (seg == 1) Wsrc = Wi + (long)(6 + gate) * 262144 + cig;  // Wi[1][0]
    else               Wsrc = Wh + (long)(6 + gate) * 262144 + cig;  // Wh[1][0]

    // one-time weight stage: global -> TF32 -> smem (resident for all steps)
#pragma unroll 4
    for (int i = 0; i < 32; i++) {
        int f = tid + i * 128;
        int kk = f >> 3, c4 = (f & 7) << 2;
        float4 w = *(const float4*)(Wsrc + (long)kk * 512 + c4);
        uint4 u;
        u.x = f2tf(w.x); u.y = f2tf(w.y); u.z = f2tf(w.z); u.w = f2tf(w.w);
        *(uint4*)(Bs + kk * BSTR + c4) = u;
    }

    // static elementwise assignment (ESLOT slots, strided by NTHR)
    const float* b2 = bv + 2 * NG3;   // b[1][0]
    const int tg = ct * 128 + tid;
    int  e_half[ESLOT], e_b[ESLOT], e_u[ESLOT];
    bool e_v[ESLOT];
    float e_b2r[ESLOT], e_b2z[ESLOT], e_b2n[ESLOT];
#pragma unroll
    for (int e = 0; e < ESLOT; e++) {
        int it = tg + e * NTHR;
        e_v[e] = (it < EWTOT);
        int ith = e_v[e] ? it : 0;
        e_half[e] = ith >> 15;
        e_b[e]    = (ith >> 9) & 63;
        e_u[e]    = ith & 511;
        e_b2r[e] = e_b2z[e] = e_b2n[e] = 0.f;
        if (e_v[e] && e_half[e]) {
            e_b2r[e] = __ldg(b2 + e_u[e]);
            e_b2z[e] = __ldg(b2 + 512 + e_u[e]);
            e_b2n[e] = __ldg(b2 + 1024 + e_u[e]);
        }
    }

    const unsigned as_base = (unsigned)__cvta_generic_to_shared(As);
    unsigned bt = 0;                      // barrier target counter
    __syncthreads();

    for (int k = 0; k <= SS; k++) {
        const int rd = k & 1, wr = rd ^ 1;
        const float4* hsrc = (const float4*)g_ha[rd][(seg == 2) ? 1 : 0];

        // A-fill in two K-halves (cp.async), second half overlapped with MMA
#pragma unroll
        for (int half = 0; half < 2; half++) {
#pragma unroll 8
            for (int i = 0; i < 32; i++) {
                int u = tid + i * 128;            // [0,4096) 16B units per half
                int row = u >> 6, c4 = u & 63;
                cpasync16(as_base + (unsigned)(row * ASTR + half * 256 + c4 * 4) * 4u,
                          hsrc + row * 128 + half * 64 + c4);
            }
            cpasync_commit();
        }

        float acc[2][2][4];
#pragma unroll
        for (int a = 0; a < 2; a++)
#pragma unroll
            for (int b = 0; b < 2; b++)
#pragma unroll
                for (int c = 0; c < 4; c++) acc[a][b][c] = 0.f;

        const unsigned* ApA = As + (wm * 32 + gq) * ASTR;
        const unsigned* Bp0 = Bs + wn * 16 + gq;
        const unsigned* Bp1 = Bp0 + 8;

#pragma unroll
        for (int half = 0; half < 2; half++) {
            if (half == 0) cpasync_wait<1>(); else cpasync_wait<0>();
            __syncthreads();
#pragma unroll 4
            for (int k8 = 0; k8 < 32; k8++) {
                const int kb = half * 256 + k8 * 8;
                unsigned a0[4], a1[4];
                a0[0] = ApA[kb + tq];
                a0[1] = ApA[8 * ASTR + kb + tq];
                a0[2] = ApA[kb + 4 + tq];
                a0[3] = ApA[8 * ASTR + kb + 4 + tq];
                a1[0] = ApA[16 * ASTR + kb + tq];
                a1[1] = ApA[24 * ASTR + kb + tq];
                a1[2] = ApA[16 * ASTR + kb + 4 + tq];
                a1[3] = ApA[24 * ASTR + kb + 4 + tq];
                unsigned b00 = Bp0[(kb + tq) * BSTR];
                unsigned b01 = Bp0[(kb + 4 + tq) * BSTR];
                unsigned b10 = Bp1[(kb + tq) * BSTR];
                unsigned b11 = Bp1[(kb + 4 + tq) * BSTR];
                mma8(acc[0][0], a0, b00, b01);
                mma8(acc[1][0], a1, b00, b01);
                mma8(acc[0][1], a0, b10, b11);
                mma8(acc[1][1], a1, b10, b11);
            }
        }

        // write G tile (L2 only)
        {
            int colb = ct * 32 + wn * 16;
#pragma unroll
            for (int mf = 0; mf < 2; mf++)
#pragma unroll
                for (int nf = 0; nf < 2; nf++) {
                    int row = wm * 32 + mf * 16 + gq;
                    int col = colb + nf * 8 + tq * 2;
                    __stcg((float2*)(g_G + (long)row * STEPN + col),
                           make_float2(acc[mf][nf][0], acc[mf][nf][1]));
                    __stcg((float2*)(g_G + (long)(row + 8) * STEPN + col),
                           make_float2(acc[mf][nf][2], acc[mf][nf][3]));
                }
        }

        // prefetch G-independent EW operands (latency hidden by barrier wait)
        float pf_xr[ESLOT], pf_xz[ESLOT], pf_xn[ESLOT], pf_hp[ESLOT];
#pragma unroll
        for (int e = 0; e < ESLOT; e++) {
            pf_xr[e] = pf_xz[e] = pf_xn[e] = pf_hp[e] = 0.f;
            if (e_v[e]) {
                if (e_half[e] == 0) {
                    if (k < SS) {
                        const float* xs = g_xs1 + ((long)k * BB + e_b[e]) * NG3 + e_u[e];
                        pf_xr[e] = __ldcg(xs);
                        pf_xz[e] = __ldcg(xs + 512);
                        pf_xn[e] = __ldcg(xs + 1024);
                        pf_hp[e] = __ldcg(&g_h[rd][0][e_b[e] * HH + e_u[e]]);
                    }
                } else if (k >= 1) {
                    pf_hp[e] = __ldcg(&g_h[rd][1][e_b[e] * HH + e_u[e]]);
                }
            }
        }

        grid_bar(++bt, ct);   // G visible everywhere

        // elementwise GRU updates
#pragma unroll
        for (int e = 0; e < ESLOT; e++) {
            if (!e_v[e]) continue;
            const float* G = g_G + e_b[e] * STEPN;
            const int u = e_u[e];
            const int idx = e_b[e] * HH + u;
            if (e_half[e] == 0) {
                if (k < SS) {
                    float gr = __ldcg(G + u);
                    float gz = __ldcg(G + 512 + u);
                    float gn = __ldcg(G + 1024 + u);
                    float r  = sigm(pf_xr[e] + gr);
                    float z  = sigm(pf_xz[e] + gz);
                    float nn = tanh_fast(pf_xn[e] + r * gn);
                    float v  = (1.f - z) * nn + z * pf_hp[e];
                    __stcg(&g_h[wr][0][idx], v);
                    __stcg(&g_ha[wr][0][idx], __uint_as_float(f2tf(v)));
                }
            } else if (k >= 1) {
                float xr = __ldcg(G + 1536 + u) + e_b2r[e];
                float xz = __ldcg(G + 2048 + u) + e_b2z[e];
                float xn = __ldcg(G + 2560 + u) + e_b2n[e];
                float r2 = sigm(xr + __ldcg(G + 3072 + u));
                float z2 = sigm(xz + __ldcg(G + 3584 + u));
                float n2 = tanh_fast(xn + r2 * __ldcg(G + 4096 + u));
                float v  = (1.f - z2) * n2 + z2 * pf_hp[e];
                __stcg(&g_h[wr][1][idx], v);
                __stcg(&g_ha[wr][1][idx], __uint_as_float(f2tf(v)));
                if (k == SS) __stcg(&g_fcin[e_b[e] * (2 * HH) + u], v);
            }
        }

        grid_bar(++bt, ct);   // h visible everywhere before next step
    }
}

// backward step 1 projection: x[:,1023,:] @ Wi[0][1] + b[0][1]
__global__ __launch_bounds__(128) void k_gb1(const float* __restrict__ x,
                                             const float* __restrict__ Wi,
                                             const float* __restrict__ bv)
{
    int n = blockIdx.x * 64;
    int gate = n >> 9, cig = n & 511;
    const float* A = x + (long)(SS - 1) * II;
    const float* B512 = Wi + ((long)(1 * 3 + gate)) * 512 * 512 + cig;   // Wi[0][1]
    gemm_core(A, (long)SS * II, B512, 512, bv + 1 * NG3 + n, g_gb1 + n, NG3);
}

__global__ void k_ewb1()
{
    int b = blockIdx.x, u = threadIdx.x;
    float z  = sigm(g_gb1[b * NG3 + 512 + u]);
    float nn = tanh_fast(g_gb1[b * NG3 + 1024 + u]);
    g_h1b[b * HH + u] = (1.f - z) * nn;
}

// backward step 2 projection: h1b @ Wi[1][1] + b[1][1]
__global__ __launch_bounds__(128) void k_gb2(const float* __restrict__ Wi,
                                             const float* __restrict__ bv)
{
    int n = blockIdx.x * 64;
    int gate = n >> 9, cig = n & 511;
    const float* B512 = Wi + ((long)(3 * 3 + gate)) * 512 * 512 + cig;   // Wi[1][1]
    gemm_core(g_h1b, HH, B512, 512, bv + 3 * NG3 + n, g_gb2 + n, NG3);
}

__global__ void k_ewb2()
{
    int b = blockIdx.x, u = threadIdx.x;
    float z  = sigm(g_gb2[b * NG3 + 512 + u]);
    float nn = tanh_fast(g_gb2[b * NG3 + 1024 + u]);
    g_fcin[b * (2 * HH) + HH + u] = (1.f - z) * nn;
}

// final FC: out[64,512] = fcin[64,1024] @ fc_w + fc_b
__global__ __launch_bounds__(128) void k_fc(const float* __restrict__ fw,
                                            const float* __restrict__ fb,
                                            float* __restrict__ out)
{
    int n = blockIdx.x * 64;
    gemm_core(g_fcin, 2 * HH, fw + n, 2 * HH, fb + n, out + n, HH);
}

// ---------------- launch ------------------------------------------------------
extern "C" void kernel_launch(void* const* d_in, const int* in_sizes, int n_in,
                              void* d_out, int out_size)
{
    const float* x  = (const float*)d_in[0];
    const float* Wi = (const float*)d_in[1];
    const float* Wh = (const float*)d_in[2];
    const float* bv = (const float*)d_in[3];
    const float* fw = (const float*)d_in[4];
    const float* fb = (const float*)d_in[5];
    float* out = (float*)d_out;

    cudaFuncSetAttribute(k_scan, cudaFuncAttributeMaxDynamicSharedMemorySize, SCAN_SMEM);

    k_zero<<<64, 256>>>();                       // launch 1

    dim3 gp(NG3 / 64, SS);
    k_proj<<<gp, 128>>>(x, Wi, bv);              // launch 2

    // backward direction pieces independent of the scan
    k_gb1<<<NG3 / 64, 128>>>(x, Wi, bv);         // launch 3
    k_ewb1<<<BB, HH>>>();                        // launch 4
    k_gb2<<<NG3 / 64, 128>>>(Wi, bv);            // launch 5

    // forward scan: launch 6
    k_scan<<<NCTA, 128, SCAN_SMEM>>>(Wi, Wh, bv);

    k_ewb2<<<BB, HH>>>();                        // launch 7
    k_fc<<<HH / 64, 128>>>(fw, fb, out);         // launch 8
}

// round 6
// speedup vs baseline: 1.3926x; 1.3926x over previous
#include <cuda_runtime.h>
#include <cuda_bf16.h>

// Problem constants
#define BB   64
#define SS   1024
#define II   512
#define HH   512
#define NG3  1536          // 3*H
#define NCTA 96            // 32 layer-1 CTAs + 64 layer-2 CTAs
#define L1CTA 32
// smem layout (words): B_perm 24576 (98304 B) + A double buffer 32768 (131072 B)
#define BWORDS 24576
#define AWORDS 32768       // 2 halves x 16384
#define SCAN_SMEM ((BWORDS + AWORDS) * 4)   // 229376 B (<= 232448)

// ---------------- static device scratch --------------------------------------
__device__ float g_xs1[(long)SS * BB * NG3];     // layer-1 input projections [s][b][3H]
__device__ float g_h[2][2][BB * HH];             // fp32 h [pingpong][layer][b*H]
__device__ float g_haperm[2][2][BB * HH];        // tf32 h in A-fragment-permuted layout
__device__ float g_gb1[BB * NG3];
__device__ float g_gb2[BB * NG3];
__device__ float g_h1b[BB * HH];
__device__ float g_fcin[BB * 2 * HH];            // [b][fwd H | bwd H]

__device__ unsigned g_cnt = 0;                   // grid barrier arrival count
__device__ unsigned g_gen = 0;                   // grid barrier generation

// ---------------- helpers ----------------------------------------------------
__device__ __forceinline__ unsigned f2tf(float f) {
    unsigned u;
    asm("cvt.rna.tf32.f32 %0, %1;" : "=r"(u) : "f"(f));
    return u;
}

__device__ __forceinline__ void mma8(float c[4], const unsigned a[4], unsigned b0, unsigned b1) {
    asm volatile(
        "mma.sync.aligned.m16n8k8.row.col.f32.tf32.tf32.f32 "
        "{%0,%1,%2,%3},{%4,%5,%6,%7},{%8,%9},{%0,%1,%2,%3};"
        : "+f"(c[0]), "+f"(c[1]), "+f"(c[2]), "+f"(c[3])
        : "r"(a[0]), "r"(a[1]), "r"(a[2]), "r"(a[3]), "r"(b0), "r"(b1));
}

__device__ __forceinline__ float sigm(float v) { return 1.f / (1.f + __expf(-v)); }
__device__ __forceinline__ float tanh_fast(float v) {
    return 1.f - 2.f / (1.f + __expf(2.f * v));
}

__device__ __forceinline__ void cpasync16(unsigned saddr, const void* g) {
    asm volatile("cp.async.cg.shared.global [%0], [%1], 16;" :: "r"(saddr), "l"(g));
}
__device__ __forceinline__ void cpasync_commit() {
    asm volatile("cp.async.commit_group;" ::: "memory");
}
template<int N>
__device__ __forceinline__ void cpasync_wait() {
    asm volatile("cp.async.wait_group %0;" :: "n"(N) : "memory");
}

// A-fragment permuted index for h element (b, u)
__device__ __forceinline__ int pidx(int b, int u) {
    return (((u >> 3) * 4 + (b >> 4)) * 32 + (b & 7) * 4 + (u & 3)) * 4
           + ((u >> 2) & 1) * 2 + ((b >> 3) & 1);
}

// atomic grid barrier (R3-proven): leader-only fence, arrival atomic, gen release
__device__ __forceinline__ void grid_bar() {
    __syncthreads();
    if (threadIdx.x == 0) {
        __threadfence();
        unsigned gen;
        asm volatile("ld.acquire.gpu.u32 %0, [%1];" : "=r"(gen) : "l"(&g_gen) : "memory");
        if (atomicAdd(&g_cnt, 1) == NCTA - 1) {
            atomicExch(&g_cnt, 0);
            asm volatile("st.release.gpu.u32 [%0], %1;" :: "l"(&g_gen), "r"(gen + 1) : "memory");
        } else {
            unsigned cur;
            do {
                asm volatile("ld.acquire.gpu.u32 %0, [%1];" : "=r"(cur) : "l"(&g_gen) : "memory");
            } while (cur == gen);
        }
    }
    __syncthreads();
}

// ---------------- 64x64 TF32 GEMM core (non-scan kernels) --------------------
__device__ __forceinline__ void gemm_core(const float* __restrict__ A, long lda,
                                          const float* __restrict__ B512, int K,
                                          const float* __restrict__ bias,
                                          float* __restrict__ C, int ldc)
{
    __shared__ unsigned As[64][33];
    __shared__ unsigned Bs[32][65];

    const int tid  = threadIdx.x;
    const int lane = tid & 31;
    const int warp = tid >> 5;
    const int wm = warp >> 1, wn = warp & 1;
    const int g = lane >> 2, t = lane & 3;

    float acc[2][4][4];
#pragma unroll
    for (int a = 0; a < 2; a++)
#pragma unroll
        for (int b = 0; b < 4; b++)
#pragma unroll
            for (int c = 0; c < 4; c++) acc[a][b][c] = 0.f;

    float4 ra[4], rbv[4];
#pragma unroll
    for (int i = 0; i < 4; i++) {
        int f = tid + i * 128;
        ra[i]  = *(const float4*)(A + (long)(f >> 3) * lda + ((f & 7) << 2));
        rbv[i] = *(const float4*)(B512 + (long)(f >> 4) * 512 + ((f & 15) << 2));
    }

    for (int kc = 0; kc < K; kc += 32) {
#pragma unroll
        for (int i = 0; i < 4; i++) {
            int f = tid + i * 128;
            int r = f >> 3, cc = (f & 7) << 2;
            As[r][cc + 0] = f2tf(ra[i].x);
            As[r][cc + 1] = f2tf(ra[i].y);
            As[r][cc + 2] = f2tf(ra[i].z);
            As[r][cc + 3] = f2tf(ra[i].w);
            int bk = f >> 4, bc = (f & 15) << 2;
            Bs[bk][bc + 0] = f2tf(rbv[i].x);
            Bs[bk][bc + 1] = f2tf(rbv[i].y);
            Bs[bk][bc + 2] = f2tf(rbv[i].z);
            Bs[bk][bc + 3] = f2tf(rbv[i].w);
        }
        __syncthreads();

        if (kc + 32 < K) {
#pragma unroll
            for (int i = 0; i < 4; i++) {
                int f = tid + i * 128;
                ra[i]  = *(const float4*)(A + (long)(f >> 3) * lda + (kc + 32) + ((f & 7) << 2));
                rbv[i] = *(const float4*)(B512 + (long)(kc + 32 + (f >> 4)) * 512 + ((f & 15) << 2));
            }
        }

#pragma unroll
        for (int ks = 0; ks < 4; ks++) {
            int kb = ks * 8;
            unsigned afr[2][4];
#pragma unroll
            for (int mf = 0; mf < 2; mf++) {
                int rb_ = wm * 32 + mf * 16;
                afr[mf][0] = As[rb_ + g][kb + t];
                afr[mf][1] = As[rb_ + 8 + g][kb + t];
                afr[mf][2] = As[rb_ + g][kb + 4 + t];
                afr[mf][3] = As[rb_ + 8 + g][kb + 4 + t];
            }
#pragma unroll
            for (int nf = 0; nf < 4; nf++) {
                int cb = wn * 32 + nf * 8;
                unsigned b0 = Bs[kb + t][cb + g];
                unsigned b1 = Bs[kb + 4 + t][cb + g];
                mma8(acc[0][nf], afr[0], b0, b1);
                mma8(acc[1][nf], afr[1], b0, b1);
            }
        }
        __syncthreads();
    }

#pragma unroll
    for (int mf = 0; mf < 2; mf++)
#pragma unroll
        for (int nf = 0; nf < 4; nf++) {
            int row = wm * 32 + mf * 16 + g;
            int col = wn * 32 + nf * 8 + t * 2;
            float b0v = bias ? bias[col] : 0.f;
            float b1v = bias ? bias[col + 1] : 0.f;
            C[(long)row * ldc + col]           = acc[mf][nf][0] + b0v;
            C[(long)row * ldc + col + 1]       = acc[mf][nf][1] + b1v;
            C[(long)(row + 8) * ldc + col]     = acc[mf][nf][2] + b0v;
            C[(long)(row + 8) * ldc + col + 1] = acc[mf][nf][3] + b1v;
        }
}

// ---------------- kernels -----------------------------------------------------

__global__ void k_zero() {
    long n = 2L * 2 * BB * HH;
    float* p = &g_h[0][0][0];
    float* q = &g_haperm[0][0][0];
    for (long i = blockIdx.x * blockDim.x + threadIdx.x; i < n; i += (long)gridDim.x * blockDim.x) {
        p[i] = 0.f;
        q[i] = 0.f;
    }
}

// xs1[s][b][n] = x[b][s][:] @ Wi[0][0][gate] + b[0][0]
__global__ __launch_bounds__(128) void k_proj(const float* __restrict__ x,
                                              const float* __restrict__ Wi,
                                              const float* __restrict__ bv)
{
    int n = blockIdx.x * 64;
    int s = blockIdx.y;
    int gate = n >> 9, cig = n & 511;
    const float* A = x + (long)s * II;
    const float* B512 = Wi + ((long)(0 * 3 + gate)) * 512 * 512 + cig;   // Wi[0][0]
    gemm_core(A, (long)SS * II, B512, 512, bv + n,
              g_xs1 + ((long)s * BB) * NG3 + n, NG3);
}

// ---------------- persistent scan kernel --------------------------------------
// 96 CTAs x 128 threads (4 warps of 16 rows each).
// Layer-1 CTA (ct<32): owns 16 u's -> 48 cols of h1@Wh1 (3 gates x 16 u).
// Layer-2 CTA: owns 8 u's -> two 24-col sub-GEMMs: h1@Wi2 and h2@Wh2.
// All gate values for a CTA's units live in its own accumulators -> EW is local,
// only ONE grid barrier per step (h publish).
__global__ void __launch_bounds__(128, 1) k_scan(const float* __restrict__ Wi,
                                                 const float* __restrict__ Wh,
                                                 const float* __restrict__ bv)
{
    extern __shared__ unsigned smemu[];
    unsigned* Bsm = smemu;               // B_perm: [(k8*6+nf)*32+lane]*2+w
    unsigned* Asm = smemu + BWORDS;      // 2 x 16384 words (A fragment-permuted)

    const int tid  = threadIdx.x;
    const int lane = tid & 31;
    const int warp = tid >> 5;           // rows warp*16 .. +15
    const int g = lane >> 2, t = lane & 3;
    const int ct = blockIdx.x;
    const bool isL1 = (ct < L1CTA);
    const int u0 = isL1 ? ct * 16 : (ct - L1CTA) * 8;

    // ---- one-time weight stage into B_perm (tf32) ----
    for (int widx = tid; widx < BWORDS; widx += 128) {
        int w2 = widx & 1;
        int lane2 = (widx >> 1) & 31;
        int m = widx >> 6;               // k8*6 + nf
        int nf = m % 6, k8 = m / 6;
        int g2 = lane2 >> 2, tq2 = lane2 & 3;
        int kk = k8 * 8 + tq2 + 4 * w2;
        int gate = (nf < 3) ? nf : nf - 3;
        const float* srcW;
        int ucol;
        if (isL1) {
            int uh = (nf < 3) ? 0 : 1;
            ucol = u0 + uh * 8 + g2;
            srcW = Wh + (long)gate * 262144;                 // Wh[0][0][gate]
        } else {
            ucol = u0 + g2;
            srcW = ((nf < 3) ? Wi : Wh) + (long)(6 + gate) * 262144;  // Wi[1][0]/Wh[1][0]
        }
        Bsm[widx] = f2tf(srcW[(long)kk * 512 + ucol]);
    }

    // layer-2 bias prefetch (b[1][0]) for this thread's u's
    const float* b2 = bv + 2 * NG3;
    float b2r[2], b2z[2], b2n[2];
    if (!isL1) {
#pragma unroll
        for (int jl = 0; jl < 2; jl++) {
            int u = u0 + t * 2 + jl;
            b2r[jl] = __ldg(b2 + u);
            b2z[jl] = __ldg(b2 + 512 + u);
            b2n[jl] = __ldg(b2 + 1024 + u);
        }
    }

    const unsigned abase = (unsigned)__cvta_generic_to_shared(Asm);
    const int NPH = isL1 ? 2 : 4;
    __syncthreads();

    for (int k = 0; k <= SS; k++) {
        const int rd = k & 1, wr = rd ^ 1;

        // phase p: A source layer + k-half
        //   L1: p0 = h1 k[0,256), p1 = h1 k[256,512)       (nf 0..5)
        //   L2: p0,p1 = h1 halves (nf 0..2); p2,p3 = h2 halves (nf 3..5)
        const float* hp0 = g_haperm[rd][0];
        const float* hp1 = g_haperm[rd][1];

        // issue fill for phase 0
        {
            const float* src = hp0;      // both L1 and L2 start with h1 half 0
#pragma unroll 8
            for (int i = 0; i < 32; i++) {
                int u16 = tid + i * 128;
                cpasync16(abase + (unsigned)(u16 * 16),
                          src + u16 * 4);
            }
            cpasync_commit();
        }

        // EW operand prefetch (independent of GEMM)
        float pf_x[2][2][2][3];          // [j2][uh][jl][gate] for L1
        float pf_hp[2][2][2];            // [j2][uh or 0][jl]
        if (isL1) {
            if (k < SS) {
#pragma unroll
                for (int j2 = 0; j2 < 2; j2++) {
                    int b = warp * 16 + g + 8 * j2;
                    const float* xs = g_xs1 + ((long)k * BB + b) * NG3;
#pragma unroll
                    for (int uh = 0; uh < 2; uh++)
#pragma unroll
                        for (int jl = 0; jl < 2; jl++) {
                            int u = u0 + uh * 8 + t * 2 + jl;
                            pf_x[j2][uh][jl][0] = __ldcg(xs + u);
                            pf_x[j2][uh][jl][1] = __ldcg(xs + 512 + u);
                            pf_x[j2][uh][jl][2] = __ldcg(xs + 1024 + u);
                            pf_hp[j2][uh][jl]   = __ldcg(&g_h[rd][0][b * HH + u]);
                        }
                }
            }
        } else {
            if (k >= 1) {
#pragma unroll
                for (int j2 = 0; j2 < 2; j2++) {
                    int b = warp * 16 + g + 8 * j2;
#pragma unroll
                    for (int jl = 0; jl < 2; jl++) {
                        int u = u0 + t * 2 + jl;
                        pf_hp[j2][0][jl] = __ldcg(&g_h[rd][1][b * HH + u]);
                    }
                }
            }
        }

        float acc[6][4];
#pragma unroll
        for (int nf = 0; nf < 6; nf++)
#pragma unroll
            for (int c = 0; c < 4; c++) acc[nf][c] = 0.f;

        for (int p = 0; p < NPH; p++) {
            // issue next fill
            if (p + 1 < NPH) {
                const float* src;
                if (isL1) src = hp0 + 16384;               // p1: h1 half 1
                else      src = (p == 0) ? hp0 + 16384     // p1: h1 half 1
                              : (p == 1) ? hp1             // p2: h2 half 0
                                         : hp1 + 16384;    // p3: h2 half 1
                unsigned dst = abase + (unsigned)(((p + 1) & 1) * 16384 * 4);
#pragma unroll 8
                for (int i = 0; i < 32; i++) {
                    int u16 = tid + i * 128;
                    cpasync16(dst + (unsigned)(u16 * 16), src + u16 * 4);
                }
                cpasync_commit();
                cpasync_wait<1>();
            } else {
                cpasync_wait<0>();
            }
            __syncthreads();

            const int kh  = isL1 ? p : (p & 1);
            const int nfb = isL1 ? 0 : ((p < 2) ? 0 : 3);
            const int nfc = isL1 ? 6 : 3;
            const unsigned* Ab = Asm + (p & 1) * 16384;

            // only run full nf set on L1 phases; L2 runs its 3-nf slice
#pragma unroll 2
            for (int k8l = 0; k8l < 32; k8l++) {
                const int k8g = kh * 32 + k8l;
                uint4 av = *(const uint4*)(Ab + (k8l * 4 + warp) * 128 + lane * 4);
                unsigned a[4] = {av.x, av.y, av.z, av.w};
                const unsigned* Bp = Bsm + (k8g * 6) * 64 + lane * 2;
                if (isL1) {
#pragma unroll
                    for (int nf = 0; nf < 6; nf++) {
                        uint2 bb = *(const uint2*)(Bp + nf * 64);
                        mma8(acc[nf], a, bb.x, bb.y);
                    }
                } else {
#pragma unroll
                    for (int nf2 = 0; nf2 < 3; nf2++) {
                        int nf = nfb + nf2;
                        uint2 bb = *(const uint2*)(Bp + nf * 64);
                        mma8(acc[nf], a, bb.x, bb.y);
                    }
                }
            }
            __syncthreads();   // safe buffer reuse for fill(p+2)
        }

        // ---- elementwise GRU update, fully local (acc in registers) ----
        if (isL1) {
            if (k < SS) {
#pragma unroll
                for (int j2 = 0; j2 < 2; j2++) {
                    int b = warp * 16 + g + 8 * j2;
#pragma unroll
                    for (int uh = 0; uh < 2; uh++)
#pragma unroll
                        for (int jl = 0; jl < 2; jl++) {
                            int u = u0 + uh * 8 + t * 2 + jl;
                            int j = j2 * 2 + jl;
                            float r  = sigm(pf_x[j2][uh][jl][0] + acc[uh * 3 + 0][j]);
                            float z  = sigm(pf_x[j2][uh][jl][1] + acc[uh * 3 + 1][j]);
                            float nn = tanh_fast(pf_x[j2][uh][jl][2] + r * acc[uh * 3 + 2][j]);
                            float v  = (1.f - z) * nn + z * pf_hp[j2][uh][jl];
                            __stcg(&g_h[wr][0][b * HH + u], v);
                            __stcg(&g_haperm[wr][0][pidx(b, u)], __uint_as_float(f2tf(v)));
                        }
                }
            }
        } else {
            if (k >= 1) {
#pragma unroll
                for (int j2 = 0; j2 < 2; j2++) {
                    int b = warp * 16 + g + 8 * j2;
#pragma unroll
                    for (int jl = 0; jl < 2; jl++) {
                        int u = u0 + t * 2 + jl;
                        int j = j2 * 2 + jl;
                        float xr = acc[0][j] + b2r[jl];
                        float xz = acc[1][j] + b2z[jl];
                        float xn = acc[2][j] + b2n[jl];
                        float r2 = sigm(xr + acc[3][j]);
                        float z2 = sigm(xz + acc[4][j]);
                        float n2 = tanh_fast(xn + r2 * acc[5][j]);
                        float v  = (1.f - z2) * n2 + z2 * pf_hp[j2][0][jl];
                        __stcg(&g_h[wr][1][b * HH + u], v);
                        __stcg(&g_haperm[wr][1][pidx(b, u)], __uint_as_float(f2tf(v)));
                        if (k == SS) __stcg(&g_fcin[b * (2 * HH) + u], v);
                    }
                }
            }
        }

        grid_bar();   // single barrier: publish h for next step
    }
}

// backward step 1 projection: x[:,1023,:] @ Wi[0][1] + b[0][1]
__global__ __launch_bounds__(128) void k_gb1(const float* __restrict__ x,
                                             const float* __restrict__ Wi,
                                             const float* __restrict__ bv)
{
    int n = blockIdx.x * 64;
    int gate = n >> 9, cig = n & 511;
    const float* A = x + (long)(SS - 1) * II;
    const float* B512 = Wi + ((long)(1 * 3 + gate)) * 512 * 512 + cig;   // Wi[0][1]
    gemm_core(A, (long)SS * II, B512, 512, bv + 1 * NG3 + n, g_gb1 + n, NG3);
}

__global__ void k_ewb1()
{
    int b = blockIdx.x, u = threadIdx.x;
    float z  = sigm(g_gb1[b * NG3 + 512 + u]);
    float nn = tanh_fast(g_gb1[b * NG3 + 1024 + u]);
    g_h1b[b * HH + u] = (1.f - z) * nn;
}

// backward step 2 projection: h1b @ Wi[1][1] + b[1][1]
__global__ __launch_bounds__(128) void k_gb2(const float* __restrict__ Wi,
                                             const float* __restrict__ bv)
{
    int n = blockIdx.x * 64;
    int gate = n >> 9, cig = n & 511;
    const float* B512 = Wi + ((long)(3 * 3 + gate)) * 512 * 512 + cig;   // Wi[1][1]
    gemm_core(g_h1b, HH, B512, 512, bv + 3 * NG3 + n, g_gb2 + n, NG3);
}

__global__ void k_ewb2()
{
    int b = blockIdx.x, u = threadIdx.x;
    float z  = sigm(g_gb2[b * NG3 + 512 + u]);
    float nn = tanh_fast(g_gb2[b * NG3 + 1024 + u]);
    g_fcin[b * (2 * HH) + HH + u] = (1.f - z) * nn;
}

// final FC: out[64,512] = fcin[64,1024] @ fc_w + fc_b
__global__ __launch_bounds__(128) void k_fc(const float* __restrict__ fw,
                                            const float* __restrict__ fb,
                                            float* __restrict__ out)
{
    int n = blockIdx.x * 64;
    gemm_core(g_fcin, 2 * HH, fw + n, 2 * HH, fb + n, out + n, HH);
}

// ---------------- launch ------------------------------------------------------
extern "C" void kernel_launch(void* const* d_in, const int* in_sizes, int n_in,
                              void* d_out, int out_size)
{
    const float* x  = (const float*)d_in[0];
    const float* Wi = (const float*)d_in[1];
    const float* Wh = (const float*)d_in[2];
    const float* bv = (const float*)d_in[3];
    const float* fw = (const float*)d_in[4];
    const float* fb = (const float*)d_in[5];
    float* out = (float*)d_out;

    cudaFuncSetAttribute(k_scan, cudaFuncAttributeMaxDynamicSharedMemorySize, SCAN_SMEM);

    k_zero<<<64, 256>>>();                       // launch 1

    dim3 gp(NG3 / 64, SS);
    k_proj<<<gp, 128>>>(x, Wi, bv);              // launch 2

    // backward direction pieces independent of the scan
    k_gb1<<<NG3 / 64, 128>>>(x, Wi, bv);         // launch 3
    k_ewb1<<<BB, HH>>>();                        // launch 4
    k_gb2<<<NG3 / 64, 128>>>(Wi, bv);            // launch 5

    // forward scan: launch 6
    k_scan<<<NCTA, 128, SCAN_SMEM>>>(Wi, Wh, bv);

    k_ewb2<<<BB, HH>>>();                        // launch 7
    k_fc<<<HH / 64, 128>>>(fw, fb, out);         // launch 8
}

// round 7
// speedup vs baseline: 1.6391x; 1.1770x over previous
#include <cuda_runtime.h>
#include <cuda_bf16.h>

// Problem constants
#define BB   64
#define SS   1024
#define II   512
#define HH   512
#define NG3  1536          // 3*H
#define NCTA 96            // 64 type-A (layer1+Wi2) + 32 type-B (layer2 Wh2)
#define ACTA 64
// smem (words): B_perm 24576 (98304 B) + A double buffer 32768 (131072 B)
#define BWORDS 24576
#define AWORDS 32768       // 2 halves x 16384
#define SCAN_SMEM ((BWORDS + AWORDS) * 4)   // 229376 B

// ---------------- static device scratch --------------------------------------
__device__ float g_xs1[(long)SS * BB * NG3];     // layer-1 input projections [s][b][3H]
__device__ float g_xg2[2][BB * NG3];             // layer-2 input projections (pingpong)
__device__ float g_h[2][2][BB * HH];             // fp32 h [pingpong][layer][b*H]
__device__ float g_haperm[2][2][BB * HH];        // tf32 h in A-fragment-permuted layout
__device__ float g_gb1[BB * NG3];
__device__ float g_gb2[BB * NG3];
__device__ float g_h1b[BB * HH];
__device__ float g_fcin[BB * 2 * HH];            // [b][fwd H | bwd H]

__device__ unsigned g_grp[12];                   // monotonic group arrival counters
__device__ unsigned g_root = 0;                  // monotonic root counter
__device__ unsigned g_gen = 0;                   // barrier generation

// ---------------- helpers ----------------------------------------------------
__device__ __forceinline__ unsigned f2tf(float f) {
    unsigned u;
    asm("cvt.rna.tf32.f32 %0, %1;" : "=r"(u) : "f"(f));
    return u;
}

__device__ __forceinline__ void mma8(float c[4], const unsigned a[4], unsigned b0, unsigned b1) {
    asm volatile(
        "mma.sync.aligned.m16n8k8.row.col.f32.tf32.tf32.f32 "
        "{%0,%1,%2,%3},{%4,%5,%6,%7},{%8,%9},{%0,%1,%2,%3};"
        : "+f"(c[0]), "+f"(c[1]), "+f"(c[2]), "+f"(c[3])
        : "r"(a[0]), "r"(a[1]), "r"(a[2]), "r"(a[3]), "r"(b0), "r"(b1));
}

__device__ __forceinline__ float sigm(float v) { return 1.f / (1.f + __expf(-v)); }
__device__ __forceinline__ float tanh_fast(float v) {
    return 1.f - 2.f / (1.f + __expf(2.f * v));
}

__device__ __forceinline__ void cpasync16(unsigned saddr, const void* g) {
    asm volatile("cp.async.cg.shared.global [%0], [%1], 16;" :: "r"(saddr), "l"(g));
}
__device__ __forceinline__ void cpasync_commit() {
    asm volatile("cp.async.commit_group;" ::: "memory");
}
template<int N>
__device__ __forceinline__ void cpasync_wait() {
    asm volatile("cp.async.wait_group %0;" :: "n"(N) : "memory");
}

// A-fragment permuted index for h element (b, u)
__device__ __forceinline__ int pidx(int b, int u) {
    return (((u >> 3) * 4 + (b >> 4)) * 32 + (b & 7) * 4 + (u & 3)) * 4
           + ((u >> 2) & 1) * 2 + ((b >> 3) & 1);
}

// two-level monotonic atomic-tree grid barrier (12 groups x 8 CTAs)
__device__ __forceinline__ void grid_bar(int ct) {
    __syncthreads();
    if (threadIdx.x == 0) {
        __threadfence();
        unsigned gen;
        asm volatile("ld.acquire.gpu.u32 %0, [%1];" : "=r"(gen) : "l"(&g_gen) : "memory");
        bool rel = false;
        unsigned o1 = atomicAdd(&g_grp[ct >> 3], 1);
        if ((o1 & 7u) == 7u) {
            __threadfence();
            unsigned o2 = atomicAdd(&g_root, 1);
            if (o2 % 12u == 11u) {
                __threadfence();
                asm volatile("st.release.gpu.u32 [%0], %1;"
                             :: "l"(&g_gen), "r"(gen + 1) : "memory");
                rel = true;
            }
        }
        if (!rel) {
            unsigned cur;
            do {
                asm volatile("ld.acquire.gpu.u32 %0, [%1];" : "=r"(cur) : "l"(&g_gen) : "memory");
            } while (cur == gen);
        }
    }
    __syncthreads();
}

// ---------------- 64x64 TF32 GEMM core (non-scan kernels) --------------------
__device__ __forceinline__ void gemm_core(const float* __restrict__ A, long lda,
                                          const float* __restrict__ B512, int K,
                                          const float* __restrict__ bias,
                                          float* __restrict__ C, int ldc)
{
    __shared__ unsigned As[64][33];
    __shared__ unsigned Bs[32][65];

    const int tid  = threadIdx.x;
    const int lane = tid & 31;
    const int warp = tid >> 5;
    const int wm = warp >> 1, wn = warp & 1;
    const int g = lane >> 2, t = lane & 3;

    float acc[2][4][4];
#pragma unroll
    for (int a = 0; a < 2; a++)
#pragma unroll
        for (int b = 0; b < 4; b++)
#pragma unroll
            for (int c = 0; c < 4; c++) acc[a][b][c] = 0.f;

    float4 ra[4], rbv[4];
#pragma unroll
    for (int i = 0; i < 4; i++) {
        int f = tid + i * 128;
        ra[i]  = *(const float4*)(A + (long)(f >> 3) * lda + ((f & 7) << 2));
        rbv[i] = *(const float4*)(B512 + (long)(f >> 4) * 512 + ((f & 15) << 2));
    }

    for (int kc = 0; kc < K; kc += 32) {
#pragma unroll
        for (int i = 0; i < 4; i++) {
            int f = tid + i * 128;
            int r = f >> 3, cc = (f & 7) << 2;
            As[r][cc + 0] = f2tf(ra[i].x);
            As[r][cc + 1] = f2tf(ra[i].y);
            As[r][cc + 2] = f2tf(ra[i].z);
            As[r][cc + 3] = f2tf(ra[i].w);
            int bk = f >> 4, bc = (f & 15) << 2;
            Bs[bk][bc + 0] = f2tf(rbv[i].x);
            Bs[bk][bc + 1] = f2tf(rbv[i].y);
            Bs[bk][bc + 2] = f2tf(rbv[i].z);
            Bs[bk][bc + 3] = f2tf(rbv[i].w);
        }
        __syncthreads();

        if (kc + 32 < K) {
#pragma unroll
            for (int i = 0; i < 4; i++) {
                int f = tid + i * 128;
                ra[i]  = *(const float4*)(A + (long)(f >> 3) * lda + (kc + 32) + ((f & 7) << 2));
                rbv[i] = *(const float4*)(B512 + (long)(kc + 32 + (f >> 4)) * 512 + ((f & 15) << 2));
            }
        }

#pragma unroll
        for (int ks = 0; ks < 4; ks++) {
            int kb = ks * 8;
            unsigned afr[2][4];
#pragma unroll
            for (int mf = 0; mf < 2; mf++) {
                int rb_ = wm * 32 + mf * 16;
                afr[mf][0] = As[rb_ + g][kb + t];
                afr[mf][1] = As[rb_ + 8 + g][kb + t];
                afr[mf][2] = As[rb_ + g][kb + 4 + t];
                afr[mf][3] = As[rb_ + 8 + g][kb + 4 + t];
            }
#pragma unroll
            for (int nf = 0; nf < 4; nf++) {
                int cb = wn * 32 + nf * 8;
                unsigned b0 = Bs[kb + t][cb + g];
                unsigned b1 = Bs[kb + 4 + t][cb + g];
                mma8(acc[0][nf], afr[0], b0, b1);
                mma8(acc[1][nf], afr[1], b0, b1);
            }
        }
        __syncthreads();
    }

#pragma unroll
    for (int mf = 0; mf < 2; mf++)
#pragma unroll
        for (int nf = 0; nf < 4; nf++) {
            int row = wm * 32 + mf * 16 + g;
            int col = wn * 32 + nf * 8 + t * 2;
            float b0v = bias ? bias[col] : 0.f;
            float b1v = bias ? bias[col + 1] : 0.f;
            C[(long)row * ldc + col]           = acc[mf][nf][0] + b0v;
            C[(long)row * ldc + col + 1]       = acc[mf][nf][1] + b1v;
            C[(long)(row + 8) * ldc + col]     = acc[mf][nf][2] + b0v;
            C[(long)(row + 8) * ldc + col + 1] = acc[mf][nf][3] + b1v;
        }
}

// ---------------- kernels -----------------------------------------------------

__global__ void k_zero() {
    long n = 2L * 2 * BB * HH;
    float* p = &g_h[0][0][0];
    float* q = &g_haperm[0][0][0];
    for (long i = blockIdx.x * blockDim.x + threadIdx.x; i < n; i += (long)gridDim.x * blockDim.x) {
        p[i] = 0.f;
        q[i] = 0.f;
    }
}

// xs1[s][b][n] = x[b][s][:] @ Wi[0][0][gate] + b[0][0]
__global__ __launch_bounds__(128) void k_proj(const float* __restrict__ x,
                                              const float* __restrict__ Wi,
                                              const float* __restrict__ bv)
{
    int n = blockIdx.x * 64;
    int s = blockIdx.y;
    int gate = n >> 9, cig = n & 511;
    const float* A = x + (long)s * II;
    const float* B512 = Wi + ((long)(0 * 3 + gate)) * 512 * 512 + cig;   // Wi[0][0]
    gemm_core(A, (long)SS * II, B512, 512, bv + n,
              g_xs1 + ((long)s * BB) * NG3 + n, NG3);
}

// ---------------- persistent scan kernel --------------------------------------
// 96 CTAs x 128 threads. Layer-2 pipelined TWO steps behind layer-1.
// Type A (ct<64, owns 8 u): fills h1 only; computes 3 Wh1 gate cols + 3 Wi2
//   gate cols for its u's; local layer-1 EW; stores xg2 (Wi2 proj) to global.
// Type B (ct>=64, owns 16 u): fills h2 only; computes 3 Wh2 gate cols (x2 u
//   halves); local layer-2 EW using the PREVIOUS iteration's xg2 (prefetched).
// Uniform per-CTA work, one grid barrier per iteration, 1026 iterations.
__global__ void __launch_bounds__(128, 1) k_scan(const float* __restrict__ Wi,
                                                 const float* __restrict__ Wh,
                                                 const float* __restrict__ bv)
{
    extern __shared__ unsigned smemu[];
    unsigned* Bsm = smemu;               // B_perm: ((k8*6+nf)*64 + lane*2 + w)
    unsigned* Asm = smemu + BWORDS;      // 2 x 16384 words (A fragment-permuted)

    const int tid  = threadIdx.x;
    const int lane = tid & 31;
    const int warp = tid >> 5;           // rows warp*16 .. +15
    const int g = lane >> 2, t = lane & 3;
    const int ct = blockIdx.x;
    const bool isA = (ct < ACTA);
    const int u0 = isA ? ct * 8 : (ct - ACTA) * 16;
    const int hlayer = isA ? 0 : 1;

    // ---- one-time weight stage into B_perm (tf32) ----
    for (int widx = tid; widx < BWORDS; widx += 128) {
        int w2 = widx & 1;
        int lane2 = (widx >> 1) & 31;
        int m = widx >> 6;               // k8*6 + nf
        int nf = m % 6, k8 = m / 6;
        int g2 = lane2 >> 2, tq2 = lane2 & 3;
        int kk = k8 * 8 + tq2 + 4 * w2;
        int gate = nf % 3;
        const float* srcW;
        int ucol;
        if (isA) {
            ucol = u0 + g2;
            srcW = (nf < 3) ? (Wh + (long)gate * 262144)          // Wh[0][0][gate]
                            : (Wi + (long)(6 + gate) * 262144);   // Wi[1][0][gate]
        } else {
            int uh = nf / 3;
            ucol = u0 + uh * 8 + g2;
            srcW = Wh + (long)(6 + gate) * 262144;                // Wh[1][0][gate]
        }
        Bsm[widx] = f2tf(srcW[(long)kk * 512 + ucol]);
    }

    // layer-2 bias prefetch (b[1][0]) for type-B threads' u's
    const float* b2 = bv + 2 * NG3;
    float b2r[2][2], b2z[2][2], b2n[2][2];
    if (!isA) {
#pragma unroll
        for (int uh = 0; uh < 2; uh++)
#pragma unroll
            for (int jl = 0; jl < 2; jl++) {
                int u = u0 + uh * 8 + t * 2 + jl;
                b2r[uh][jl] = __ldg(b2 + u);
                b2z[uh][jl] = __ldg(b2 + 512 + u);
                b2n[uh][jl] = __ldg(b2 + 1024 + u);
            }
    }

    const unsigned abase = (unsigned)__cvta_generic_to_shared(Asm);
    __syncthreads();

    for (int k = 0; k <= SS + 1; k++) {
        const int rd = k & 1, wr = rd ^ 1;
        const bool active = isA ? (k <= SS) : (k >= 2);

        if (active) {
            const float* hp = g_haperm[rd][hlayer];

            // issue fill for phase 0 (k-half 0 of this CTA's h source)
#pragma unroll 8
            for (int i = 0; i < 32; i++) {
                int u16 = tid + i * 128;
                cpasync16(abase + (unsigned)(u16 * 16), hp + u16 * 4);
            }
            cpasync_commit();

            // EW operand prefetch (independent of the GEMM; hidden under fill)
            float pf_x[2][2][3], pf_hpA[2][2];
            float pf_xg[2][2][2][3], pf_hpB[2][2][2];
            if (isA) {
                if (k < SS) {
#pragma unroll
                    for (int j2 = 0; j2 < 2; j2++) {
                        int b = warp * 16 + g + 8 * j2;
                        const float* xs = g_xs1 + ((long)k * BB + b) * NG3;
#pragma unroll
                        for (int jl = 0; jl < 2; jl++) {
                            int u = u0 + t * 2 + jl;
                            pf_x[j2][jl][0] = __ldcg(xs + u);
                            pf_x[j2][jl][1] = __ldcg(xs + 512 + u);
                            pf_x[j2][jl][2] = __ldcg(xs + 1024 + u);
                            pf_hpA[j2][jl]  = __ldcg(&g_h[rd][0][b * HH + u]);
                        }
                    }
                }
            } else {
                const float* xg = g_xg2[(k - 1) & 1];
#pragma unroll
                for (int j2 = 0; j2 < 2; j2++) {
                    int b = warp * 16 + g + 8 * j2;
#pragma unroll
                    for (int uh = 0; uh < 2; uh++)
#pragma unroll
                        for (int jl = 0; jl < 2; jl++) {
                            int u = u0 + uh * 8 + t * 2 + jl;
                            pf_xg[j2][uh][jl][0] = __ldcg(xg + b * NG3 + u);
                            pf_xg[j2][uh][jl][1] = __ldcg(xg + b * NG3 + 512 + u);
                            pf_xg[j2][uh][jl][2] = __ldcg(xg + b * NG3 + 1024 + u);
                            pf_hpB[j2][uh][jl]   = __ldcg(&g_h[rd][1][b * HH + u]);
                        }
                }
            }

            float acc[6][4];
#pragma unroll
            for (int nf = 0; nf < 6; nf++)
#pragma unroll
                for (int c = 0; c < 4; c++) acc[nf][c] = 0.f;

#pragma unroll
            for (int p = 0; p < 2; p++) {
                if (p == 0) {                       // issue phase-1 fill
#pragma unroll 8
                    for (int i = 0; i < 32; i++) {
                        int u16 = tid + i * 128;
                        cpasync16(abase + (unsigned)(16384 * 4) + (unsigned)(u16 * 16),
                                  hp + 16384 + u16 * 4);
                    }
                    cpasync_commit();
                    cpasync_wait<1>();
                } else {
                    cpasync_wait<0>();
                }
                __syncthreads();

                const unsigned* Ab = Asm + p * 16384;
#pragma unroll 2
                for (int k8l = 0; k8l < 32; k8l++) {
                    const int k8g = p * 32 + k8l;
                    uint4 av = *(const uint4*)(Ab + (k8l * 4 + warp) * 128 + lane * 4);
                    unsigned a[4] = {av.x, av.y, av.z, av.w};
                    const unsigned* Bp = Bsm + (k8g * 6) * 64 + lane * 2;
#pragma unroll
                    for (int nf = 0; nf < 6; nf++) {
                        uint2 bb = *(const uint2*)(Bp + nf * 64);
                        mma8(acc[nf], a, bb.x, bb.y);
                    }
                }
                __syncthreads();
            }

            // ---- elementwise, fully CTA-local ----
            if (isA) {
#pragma unroll
                for (int j2 = 0; j2 < 2; j2++) {
                    int b = warp * 16 + g + 8 * j2;
#pragma unroll
                    for (int jl = 0; jl < 2; jl++) {
                        int u = u0 + t * 2 + jl;
                        int j = j2 * 2 + jl;
                        float* xg = g_xg2[k & 1] + b * NG3 + u;
                        __stcg(xg,        acc[3][j]);
                        __stcg(xg + 512,  acc[4][j]);
                        __stcg(xg + 1024, acc[5][j]);
                        if (k < SS) {
                            float r  = sigm(pf_x[j2][jl][0] + acc[0][j]);
                            float z  = sigm(pf_x[j2][jl][1] + acc[1][j]);
                            float nn = tanh_fast(pf_x[j2][jl][2] + r * acc[2][j]);
                            float v  = (1.f - z) * nn + z * pf_hpA[j2][jl];
                            __stcg(&g_h[wr][0][b * HH + u], v);
                            __stcg(&g_haperm[wr][0][pidx(b, u)], __uint_as_float(f2tf(v)));
                        }
                    }
                }
            } else {
#pragma unroll
                for (int j2 = 0; j2 < 2; j2++) {
                    int b = warp * 16 + g + 8 * j2;
#pragma unroll
                    for (int uh = 0; uh < 2; uh++)
#pragma unroll
                        for (int jl = 0; jl < 2; jl++) {
                            int u = u0 + uh * 8 + t * 2 + jl;
                            int j = j2 * 2 + jl;
                            float xr = pf_xg[j2][uh][jl][0] + b2r[uh][jl];
                            float xz = pf_xg[j2][uh][jl][1] + b2z[uh][jl];
                            float xn = pf_xg[j2][uh][jl][2] + b2n[uh][jl];
                            float r2 = sigm(xr + acc[uh * 3 + 0][j]);
                            float z2 = sigm(xz + acc[uh * 3 + 1][j]);
                            float n2 = tanh_fast(xn + r2 * acc[uh * 3 + 2][j]);
                            float v  = (1.f - z2) * n2 + z2 * pf_hpB[j2][uh][jl];
                            __stcg(&g_h[wr][1][b * HH + u], v);
                            __stcg(&g_haperm[wr][1][pidx(b, u)], __uint_as_float(f2tf(v)));
                            if (k == SS + 1) __stcg(&g_fcin[b * (2 * HH) + u], v);
                        }
                }
            }
        }

        grid_bar(ct);   // publish h (and xg2) for the next iteration
    }
}

// backward step 1 projection: x[:,1023,:] @ Wi[0][1] + b[0][1]
__global__ __launch_bounds__(128) void k_gb1(const float* __restrict__ x,
                                             const float* __restrict__ Wi,
                                             const float* __restrict__ bv)
{
    int n = blockIdx.x * 64;
    int gate = n >> 9, cig = n & 511;
    const float* A = x + (long)(SS - 1) * II;
    const float* B512 = Wi + ((long)(1 * 3 + gate)) * 512 * 512 + cig;   // Wi[0][1]
    gemm_core(A, (long)SS * II, B512, 512, bv + 1 * NG3 + n, g_gb1 + n, NG3);
}

__global__ void k_ewb1()
{
    int b = blockIdx.x, u = threadIdx.x;
    float z  = sigm(g_gb1[b * NG3 + 512 + u]);
    float nn = tanh_fast(g_gb1[b * NG3 + 1024 + u]);
    g_h1b[b * HH + u] = (1.f - z) * nn;
}

// backward step 2 projection: h1b @ Wi[1][1] + b[1][1]
__global__ __launch_bounds__(128) void k_gb2(const float* __restrict__ Wi,
                                             const float* __restrict__ bv)
{
    int n = blockIdx.x * 64;
    int gate = n >> 9, cig = n & 511;
    const float* B512 = Wi + ((long)(3 * 3 + gate)) * 512 * 512 + cig;   // Wi[1][1]
    gemm_core(g_h1b, HH, B512, 512, bv + 3 * NG3 + n, g_gb2 + n, NG3);
}

__global__ void k_ewb2()
{
    int b = blockIdx.x, u = threadIdx.x;
    float z  = sigm(g_gb2[b * NG3 + 512 + u]);
    float nn = tanh_fast(g_gb2[b * NG3 + 1024 + u]);
    g_fcin[b * (2 * HH) + HH + u] = (1.f - z) * nn;
}

// final FC: out[64,512] = fcin[64,1024] @ fc_w + fc_b
__global__ __launch_bounds__(128) void k_fc(const float* __restrict__ fw,
                                            const float* __restrict__ fb,
                                            float* __restrict__ out)
{
    int n = blockIdx.x * 64;
    gemm_core(g_fcin, 2 * HH, fw + n, 2 * HH, fb + n, out + n, HH);
}

// ---------------- launch ------------------------------------------------------
extern "C" void kernel_launch(void* const* d_in, const int* in_sizes, int n_in,
                              void* d_out, int out_size)
{
    const float* x  = (const float*)d_in[0];
    const float* Wi = (const float*)d_in[1];
    const float* Wh = (const float*)d_in[2];
    const float* bv = (const float*)d_in[3];
    const float* fw = (const float*)d_in[4];
    const float* fb = (const float*)d_in[5];
    float* out = (float*)d_out;

    cudaFuncSetAttribute(k_scan, cudaFuncAttributeMaxDynamicSharedMemorySize, SCAN_SMEM);

    k_zero<<<64, 256>>>();                       // launch 1

    dim3 gp(NG3 / 64, SS);
    k_proj<<<gp, 128>>>(x, Wi, bv);              // launch 2

    // backward direction pieces independent of the scan
    k_gb1<<<NG3 / 64, 128>>>(x, Wi, bv);         // launch 3
    k_ewb1<<<BB, HH>>>();                        // launch 4
    k_gb2<<<NG3 / 64, 128>>>(Wi, bv);            // launch 5

    // forward scan: launch 6
    k_scan<<<NCTA, 128, SCAN_SMEM>>>(Wi, Wh, bv);

    k_ewb2<<<BB, HH>>>();                        // launch 7
    k_fc<<<HH / 64, 128>>>(fw, fb, out);         // launch 8
}

// round 8
// speedup vs baseline: 1.6743x; 1.0214x over previous
#include <cuda_runtime.h>
#include <cuda_bf16.h>

// Problem constants
#define BB   64
#define SS   1024
#define II   512
#define HH   512
#define NG3  1536          // 3*H
#define NCTA 96            // 3 classes x 32 CTAs
// smem (words): B_perm 24576 (96KB) + A double buffer 32768 (128KB)
#define BWORDS 24576
#define AWORDS 32768
#define SCAN_SMEM ((BWORDS + AWORDS) * 4)   // 229376 B

// ---------------- static device scratch --------------------------------------
__device__ float g_xs1[(long)SS * BB * NG3];     // layer-1 input projections
__device__ float g_h1perm[4][BB * HH];           // tf32 h1 ring (perm layout)
__device__ float g_h2perm[2][BB * HH];           // tf32 h2 pingpong (perm layout)
__device__ float g_xg2r[4][BB * NG3];            // layer-2 input projection ring
__device__ float g_gb1[BB * NG3];
__device__ float g_gb2[BB * NG3];
__device__ float g_h1b[BB * HH];
__device__ float g_fcin[BB * 2 * HH];            // [b][fwd H | bwd H]

// per-class barrier state (padded to separate lines)
__device__ unsigned g_cntA[32], g_genA[32];
__device__ unsigned g_cntB1[32], g_genB1[32];
__device__ unsigned g_cntB2[32], g_genB2[32];

// ---------------- helpers ----------------------------------------------------
__device__ __forceinline__ unsigned f2tf(float f) {
    unsigned u;
    asm("cvt.rna.tf32.f32 %0, %1;" : "=r"(u) : "f"(f));
    return u;
}

__device__ __forceinline__ void mma8(float c[4], const unsigned a[4], unsigned b0, unsigned b1) {
    asm volatile(
        "mma.sync.aligned.m16n8k8.row.col.f32.tf32.tf32.f32 "
        "{%0,%1,%2,%3},{%4,%5,%6,%7},{%8,%9},{%0,%1,%2,%3};"
        : "+f"(c[0]), "+f"(c[1]), "+f"(c[2]), "+f"(c[3])
        : "r"(a[0]), "r"(a[1]), "r"(a[2]), "r"(a[3]), "r"(b0), "r"(b1));
}

__device__ __forceinline__ float sigm(float v) { return 1.f / (1.f + __expf(-v)); }
__device__ __forceinline__ float tanh_fast(float v) {
    return 1.f - 2.f / (1.f + __expf(2.f * v));
}

__device__ __forceinline__ void cpasync16(unsigned saddr, const void* g) {
    asm volatile("cp.async.cg.shared.global [%0], [%1], 16;" :: "r"(saddr), "l"(g));
}
__device__ __forceinline__ void cpasync_commit() {
    asm volatile("cp.async.commit_group;" ::: "memory");
}
template<int N>
__device__ __forceinline__ void cpasync_wait() {
    asm volatile("cp.async.wait_group %0;" :: "n"(N) : "memory");
}

// A-fragment permuted index for h element (b, u)
__device__ __forceinline__ int pidx(int b, int u) {
    return (((u >> 3) * 4 + (b >> 4)) * 32 + (b & 7) * 4 + (u & 3)) * 4
           + ((u >> 2) & 1) * 2 + ((b >> 3) & 1);
}

// 32-CTA class barrier, absolute monotonic target (counters reset by k_zero)
__device__ __forceinline__ void class_bar(unsigned* cnt, unsigned* gen, unsigned target) {
    __syncthreads();
    if (threadIdx.x == 0) {
        __threadfence();
        unsigned old = atomicAdd(cnt, 1);
        if ((old & 31u) == 31u) {
            __threadfence();
            asm volatile("st.release.gpu.u32 [%0], %1;" :: "l"(gen), "r"(target) : "memory");
        } else {
            unsigned cur;
            do {
                asm volatile("ld.acquire.gpu.u32 %0, [%1];" : "=r"(cur) : "l"(gen) : "memory");
            } while (cur < target);
        }
    }
    __syncthreads();
}

// block-wide wait until *gen >= target (cross-class progress)
__device__ __forceinline__ void wait_gen(const unsigned* gen, unsigned target) {
    if (threadIdx.x == 0) {
        unsigned cur;
        do {
            asm volatile("ld.acquire.gpu.u32 %0, [%1];" : "=r"(cur) : "l"(gen) : "memory");
        } while (cur < target);
    }
    __syncthreads();
}

// ---------------- 64x64 TF32 GEMM core (non-scan kernels) --------------------
__device__ __forceinline__ void gemm_core(const float* __restrict__ A, long lda,
                                          const float* __restrict__ B512, int K,
                                          const float* __restrict__ bias,
                                          float* __restrict__ C, int ldc)
{
    __shared__ unsigned As[64][33];
    __shared__ unsigned Bs[32][65];

    const int tid  = threadIdx.x;
    const int lane = tid & 31;
    const int warp = tid >> 5;
    const int wm = warp >> 1, wn = warp & 1;
    const int g = lane >> 2, t = lane & 3;

    float acc[2][4][4];
#pragma unroll
    for (int a = 0; a < 2; a++)
#pragma unroll
        for (int b = 0; b < 4; b++)
#pragma unroll
            for (int c = 0; c < 4; c++) acc[a][b][c] = 0.f;

    float4 ra[4], rbv[4];
#pragma unroll
    for (int i = 0; i < 4; i++) {
        int f = tid + i * 128;
        ra[i]  = *(const float4*)(A + (long)(f >> 3) * lda + ((f & 7) << 2));
        rbv[i] = *(const float4*)(B512 + (long)(f >> 4) * 512 + ((f & 15) << 2));
    }

    for (int kc = 0; kc < K; kc += 32) {
#pragma unroll
        for (int i = 0; i < 4; i++) {
            int f = tid + i * 128;
            int r = f >> 3, cc = (f & 7) << 2;
            As[r][cc + 0] = f2tf(ra[i].x);
            As[r][cc + 1] = f2tf(ra[i].y);
            As[r][cc + 2] = f2tf(ra[i].z);
            As[r][cc + 3] = f2tf(ra[i].w);
            int bk = f >> 4, bc = (f & 15) << 2;
            Bs[bk][bc + 0] = f2tf(rbv[i].x);
            Bs[bk][bc + 1] = f2tf(rbv[i].y);
            Bs[bk][bc + 2] = f2tf(rbv[i].z);
            Bs[bk][bc + 3] = f2tf(rbv[i].w);
        }
        __syncthreads();

        if (kc + 32 < K) {
#pragma unroll
            for (int i = 0; i < 4; i++) {
                int f = tid + i * 128;
                ra[i]  = *(const float4*)(A + (long)(f >> 3) * lda + (kc + 32) + ((f & 7) << 2));
                rbv[i] = *(const float4*)(B512 + (long)(kc + 32 + (f >> 4)) * 512 + ((f & 15) << 2));
            }
        }

#pragma unroll
        for (int ks = 0; ks < 4; ks++) {
            int kb = ks * 8;
            unsigned afr[2][4];
#pragma unroll
            for (int mf = 0; mf < 2; mf++) {
                int rb_ = wm * 32 + mf * 16;
                afr[mf][0] = As[rb_ + g][kb + t];
                afr[mf][1] = As[rb_ + 8 + g][kb + t];
                afr[mf][2] = As[rb_ + g][kb + 4 + t];
                afr[mf][3] = As[rb_ + 8 + g][kb + 4 + t];
            }
#pragma unroll
            for (int nf = 0; nf < 4; nf++) {
                int cb = wn * 32 + nf * 8;
                unsigned b0 = Bs[kb + t][cb + g];
                unsigned b1 = Bs[kb + 4 + t][cb + g];
                mma8(acc[0][nf], afr[0], b0, b1);
                mma8(acc[1][nf], afr[1], b0, b1);
            }
        }
        __syncthreads();
    }

#pragma unroll
    for (int mf = 0; mf < 2; mf++)
#pragma unroll
        for (int nf = 0; nf < 4; nf++) {
            int row = wm * 32 + mf * 16 + g;
            int col = wn * 32 + nf * 8 + t * 2;
            float b0v = bias ? bias[col] : 0.f;
            float b1v = bias ? bias[col + 1] : 0.f;
            C[(long)row * ldc + col]           = acc[mf][nf][0] + b0v;
            C[(long)row * ldc + col + 1]       = acc[mf][nf][1] + b1v;
            C[(long)(row + 8) * ldc + col]     = acc[mf][nf][2] + b0v;
            C[(long)(row + 8) * ldc + col + 1] = acc[mf][nf][3] + b1v;
        }
}

// ---------------- kernels -----------------------------------------------------

__global__ void k_zero() {
    long n = BB * HH;
    for (long i = blockIdx.x * blockDim.x + threadIdx.x; i < n; i += (long)gridDim.x * blockDim.x) {
        g_h1perm[0][i] = 0.f;
        g_h2perm[0][i] = 0.f;
    }
    if (blockIdx.x == 0 && threadIdx.x == 0) {
        g_cntA[0] = 0;  g_genA[0] = 0;
        g_cntB1[0] = 0; g_genB1[0] = 0;
        g_cntB2[0] = 0; g_genB2[0] = 0;
    }
}

// xs1[s][b][n] = x[b][s][:] @ Wi[0][0][gate] + b[0][0]
__global__ __launch_bounds__(128) void k_proj(const float* __restrict__ x,
                                              const float* __restrict__ Wi,
                                              const float* __restrict__ bv)
{
    int n = blockIdx.x * 64;
    int s = blockIdx.y;
    int gate = n >> 9, cig = n & 511;
    const float* A = x + (long)s * II;
    const float* B512 = Wi + ((long)(0 * 3 + gate)) * 512 * 512 + cig;   // Wi[0][0]
    gemm_core(A, (long)SS * II, B512, 512, bv + n,
              g_xs1 + ((long)s * BB) * NG3 + n, NG3);
}

// ---------------- persistent scan kernel --------------------------------------
// Three decoupled 32-CTA classes, each owns 16 u's (48 cols = 6 n-frags):
//   A  (ct 0-31):  Wh1 gates over h1(k)  -> EW layer1 -> h1(k+1) ring[4]
//   B1 (ct 32-63): Wi2 gates over h1(j+1) -> xg2[j] ring[4]      (lags A by 1)
//   B2 (ct 64-95): Wh2 gates over h2(j) + EW layer2 -> h2(j+1)   (lags B1 by 1)
// Per-class 32-CTA barriers; cross-class coupling via monotonic gen counters.
__global__ void __launch_bounds__(128, 1) k_scan(const float* __restrict__ Wi,
                                                 const float* __restrict__ Wh,
                                                 const float* __restrict__ bv)
{
    extern __shared__ unsigned smemu[];
    unsigned* Bsm = smemu;               // B_perm
    unsigned* Asm = smemu + BWORDS;      // 2 x 16384 words

    const int tid  = threadIdx.x;
    const int lane = tid & 31;
    const int warp = tid >> 5;
    const int g = lane >> 2, t = lane & 3;
    const int ct = blockIdx.x;
    const int cls = ct >> 5;             // 0=A, 1=B1, 2=B2
    const int ci  = ct & 31;
    const int u0  = ci * 16;

    // ---- one-time weight stage into B_perm (tf32); nf = uh*3 + gate ----
    const float* Wbase = (cls == 0) ? Wh : (cls == 1) ? (Wi + 6L * 262144)
                                                      : (Wh + 6L * 262144);
    for (int widx = tid; widx < BWORDS; widx += 128) {
        int w2 = widx & 1;
        int lane2 = (widx >> 1) & 31;
        int m = widx >> 6;               // k8*6 + nf
        int nf = m % 6, k8 = m / 6;
        int g2 = lane2 >> 2, tq2 = lane2 & 3;
        int kk = k8 * 8 + tq2 + 4 * w2;
        int gate = nf % 3, uh = nf / 3;
        int ucol = u0 + uh * 8 + g2;
        Bsm[widx] = f2tf(Wbase[(long)gate * 262144 + (long)kk * 512 + ucol]);
    }

    // layer-2 bias prefetch (b[1][0]) for B2
    const float* b2 = bv + 2 * NG3;
    float b2r[2][2], b2z[2][2], b2n[2][2];
    if (cls == 2) {
#pragma unroll
        for (int uh = 0; uh < 2; uh++)
#pragma unroll
            for (int jl = 0; jl < 2; jl++) {
                int u = u0 + uh * 8 + t * 2 + jl;
                b2r[uh][jl] = __ldg(b2 + u);
                b2z[uh][jl] = __ldg(b2 + 512 + u);
                b2n[uh][jl] = __ldg(b2 + 1024 + u);
            }
    }

    float hreg[2][2][2];                 // own h cells (layer1 for A, layer2 for B2)
#pragma unroll
    for (int a = 0; a < 2; a++)
#pragma unroll
        for (int b = 0; b < 2; b++)
#pragma unroll
            for (int c = 0; c < 2; c++) hreg[a][b][c] = 0.f;

    const unsigned abase = (unsigned)__cvta_generic_to_shared(Asm);
    __syncthreads();

    for (int it = 0; it < SS; it++) {
        // ---- class-specific pre-wait + fill source ----
        const float* hp;
        if (cls == 0) {
            hp = g_h1perm[it & 3];
        } else if (cls == 1) {
            wait_gen(g_genA, (unsigned)(it + 1));      // h1(it+1) visible
            hp = g_h1perm[(it + 1) & 3];
        } else {
            wait_gen(g_genB1, (unsigned)(it + 1));     // xg2[it] visible
            hp = g_h2perm[it & 1];
        }

        // issue fill phase 0
#pragma unroll 8
        for (int i = 0; i < 32; i++) {
            int u16 = tid + i * 128;
            cpasync16(abase + (unsigned)(u16 * 16), hp + u16 * 4);
        }
        cpasync_commit();

        // EW operand prefetch (hidden under fill)
        float pf_x[2][2][2][3];
        if (cls == 0) {
#pragma unroll
            for (int j2 = 0; j2 < 2; j2++) {
                int b = warp * 16 + g + 8 * j2;
                const float* xs = g_xs1 + ((long)it * BB + b) * NG3;
#pragma unroll
                for (int uh = 0; uh < 2; uh++)
#pragma unroll
                    for (int jl = 0; jl < 2; jl++) {
                        int u = u0 + uh * 8 + t * 2 + jl;
                        pf_x[j2][uh][jl][0] = __ldcg(xs + u);
                        pf_x[j2][uh][jl][1] = __ldcg(xs + 512 + u);
                        pf_x[j2][uh][jl][2] = __ldcg(xs + 1024 + u);
                    }
            }
        } else if (cls == 2) {
            const float* xg = g_xg2r[it & 3];
#pragma unroll
            for (int j2 = 0; j2 < 2; j2++) {
                int b = warp * 16 + g + 8 * j2;
#pragma unroll
                for (int uh = 0; uh < 2; uh++)
#pragma unroll
                    for (int jl = 0; jl < 2; jl++) {
                        int u = u0 + uh * 8 + t * 2 + jl;
                        pf_x[j2][uh][jl][0] = __ldcg(xg + b * NG3 + u);
                        pf_x[j2][uh][jl][1] = __ldcg(xg + b * NG3 + 512 + u);
                        pf_x[j2][uh][jl][2] = __ldcg(xg + b * NG3 + 1024 + u);
                    }
            }
        }

        // issue fill phase 1
#pragma unroll 8
        for (int i = 0; i < 32; i++) {
            int u16 = tid + i * 128;
            cpasync16(abase + (unsigned)(16384 * 4) + (unsigned)(u16 * 16),
                      hp + 16384 + u16 * 4);
        }
        cpasync_commit();

        // ---- GEMM: 2 phases x 32 k8 x 6 frags ----
        float acc[6][4];
#pragma unroll
        for (int nf = 0; nf < 6; nf++)
#pragma unroll
            for (int c = 0; c < 4; c++) acc[nf][c] = 0.f;

#pragma unroll
        for (int p = 0; p < 2; p++) {
            if (p == 0) cpasync_wait<1>(); else cpasync_wait<0>();
            __syncthreads();
            const unsigned* Ab = Asm + p * 16384;
#pragma unroll 2
            for (int k8l = 0; k8l < 32; k8l++) {
                const int k8g = p * 32 + k8l;
                uint4 av = *(const uint4*)(Ab + (k8l * 4 + warp) * 128 + lane * 4);
                unsigned a[4] = {av.x, av.y, av.z, av.w};
                const unsigned* Bp = Bsm + (k8g * 6) * 64 + lane * 2;
#pragma unroll
                for (int nf = 0; nf < 6; nf++) {
                    uint2 bb = *(const uint2*)(Bp + nf * 64);
                    mma8(acc[nf], a, bb.x, bb.y);
                }
            }
            if (p == 0) __syncthreads();
        }

        // ---- class-specific epilogue ----
        if (cls == 0) {
            if (it >= 4) wait_gen(g_genB1, (unsigned)(it - 3));   // ring slack
            float* hout = g_h1perm[(it + 1) & 3];
#pragma unroll
            for (int j2 = 0; j2 < 2; j2++) {
                int b = warp * 16 + g + 8 * j2;
#pragma unroll
                for (int uh = 0; uh < 2; uh++)
#pragma unroll
                    for (int jl = 0; jl < 2; jl++) {
                        int u = u0 + uh * 8 + t * 2 + jl;
                        int c = j2 * 2 + jl;
                        float r  = sigm(pf_x[j2][uh][jl][0] + acc[uh * 3 + 0][c]);
                        float z  = sigm(pf_x[j2][uh][jl][1] + acc[uh * 3 + 1][c]);
                        float nn = tanh_fast(pf_x[j2][uh][jl][2] + r * acc[uh * 3 + 2][c]);
                        float v  = (1.f - z) * nn + z * hreg[j2][uh][jl];
                        hreg[j2][uh][jl] = v;
                        __stcg(&hout[pidx(b, u)], __uint_as_float(f2tf(v)));
                    }
            }
            class_bar(g_cntA, g_genA, (unsigned)(it + 1));
        } else if (cls == 1) {
            if (it >= 4) wait_gen(g_genB2, (unsigned)(it - 3));   // ring slack
            float* xg = g_xg2r[it & 3];
#pragma unroll
            for (int uh = 0; uh < 2; uh++)
#pragma unroll
                for (int gate = 0; gate < 3; gate++)
#pragma unroll
                    for (int j2 = 0; j2 < 2; j2++) {
                        int b = warp * 16 + g + 8 * j2;
                        float2 val = make_float2(acc[uh * 3 + gate][j2 * 2],
                                                 acc[uh * 3 + gate][j2 * 2 + 1]);
                        __stcg((float2*)(xg + b * NG3 + gate * 512 + u0 + uh * 8 + t * 2), val);
                    }
            class_bar(g_cntB1, g_genB1, (unsigned)(it + 1));
        } else {
            float* hout = g_h2perm[(it + 1) & 1];
#pragma unroll
            for (int j2 = 0; j2 < 2; j2++) {
                int b = warp * 16 + g + 8 * j2;
#pragma unroll
                for (int uh = 0; uh < 2; uh++)
#pragma unroll
                    for (int jl = 0; jl < 2; jl++) {
                        int u = u0 + uh * 8 + t * 2 + jl;
                        int c = j2 * 2 + jl;
                        float xr = pf_x[j2][uh][jl][0] + b2r[uh][jl];
                        float xz = pf_x[j2][uh][jl][1] + b2z[uh][jl];
                        float xn = pf_x[j2][uh][jl][2] + b2n[uh][jl];
                        float r2 = sigm(xr + acc[uh * 3 + 0][c]);
                        float z2 = sigm(xz + acc[uh * 3 + 1][c]);
                        float n2 = tanh_fast(xn + r2 * acc[uh * 3 + 2][c]);
                        float v  = (1.f - z2) * n2 + z2 * hreg[j2][uh][jl];
                        hreg[j2][uh][jl] = v;
                        __stcg(&hout[pidx(b, u)], __uint_as_float(f2tf(v)));
                        if (it == SS - 1) __stcg(&g_fcin[b * (2 * HH) + u], v);
                    }
            }
            class_bar(g_cntB2, g_genB2, (unsigned)(it + 1));
        }
    }
}

// backward step 1 projection: x[:,1023,:] @ Wi[0][1] + b[0][1]
__global__ __launch_bounds__(128) void k_gb1(const float* __restrict__ x,
                                             const float* __restrict__ Wi,
                                             const float* __restrict__ bv)
{
    int n = blockIdx.x * 64;
    int gate = n >> 9, cig = n & 511;
    const float* A = x + (long)(SS - 1) * II;
    const float* B512 = Wi + ((long)(1 * 3 + gate)) * 512 * 512 + cig;   // Wi[0][1]
    gemm_core(A, (long)SS * II, B512, 512, bv + 1 * NG3 + n, g_gb1 + n, NG3);
}

__global__ void k_ewb1()
{
    int b = blockIdx.x, u = threadIdx.x;
    float z  = sigm(g_gb1[b * NG3 + 512 + u]);
    float nn = tanh_fast(g_gb1[b * NG3 + 1024 + u]);
    g_h1b[b * HH + u] = (1.f - z) * nn;
}

// backward step 2 projection: h1b @ Wi[1][1] + b[1][1]
__global__ __launch_bounds__(128) void k_gb2(const float* __restrict__ Wi,
                                             const float* __restrict__ bv)
{
    int n = blockIdx.x * 64;
    int gate = n >> 9, cig = n & 511;
    const float* B512 = Wi + ((long)(3 * 3 + gate)) * 512 * 512 + cig;   // Wi[1][1]
    gemm_core(g_h1b, HH, B512, 512, bv + 3 * NG3 + n, g_gb2 + n, NG3);
}

__global__ void k_ewb2()
{
    int b = blockIdx.x, u = threadIdx.x;
    float z  = sigm(g_gb2[b * NG3 + 512 + u]);
    float nn = tanh_fast(g_gb2[b * NG3 + 1024 + u]);
    g_fcin[b * (2 * HH) + HH + u] = (1.f - z) * nn;
}

// final FC: out[64,512] = fcin[64,1024] @ fc_w + fc_b
__global__ __launch_bounds__(128) void k_fc(const float* __restrict__ fw,
                                            const float* __restrict__ fb,
                                            float* __restrict__ out)
{
    int n = blockIdx.x * 64;
    gemm_core(g_fcin, 2 * HH, fw + n, 2 * HH, fb + n, out + n, HH);
}

// ---------------- launch ------------------------------------------------------
extern "C" void kernel_launch(void* const* d_in, const int* in_sizes, int n_in,
                              void* d_out, int out_size)
{
    const float* x  = (const float*)d_in[0];
    const float* Wi = (const float*)d_in[1];
    const float* Wh = (const float*)d_in[2];
    const float* bv = (const float*)d_in[3];
    const float* fw = (const float*)d_in[4];
    const float* fb = (const float*)d_in[5];
    float* out = (float*)d_out;

    cudaFuncSetAttribute(k_scan, cudaFuncAttributeMaxDynamicSharedMemorySize, SCAN_SMEM);

    k_zero<<<64, 256>>>();                       // launch 1

    dim3 gp(NG3 / 64, SS);
    k_proj<<<gp, 128>>>(x, Wi, bv);              // launch 2

    // backward direction pieces independent of the scan
    k_gb1<<<NG3 / 64, 128>>>(x, Wi, bv);         // launch 3
    k_ewb1<<<BB, HH>>>();                        // launch 4
    k_gb2<<<NG3 / 64, 128>>>(Wi, bv);            // launch 5

    // forward scan: launch 6
    k_scan<<<NCTA, 128, SCAN_SMEM>>>(Wi, Wh, bv);

    k_ewb2<<<BB, HH>>>();                        // launch 7
    k_fc<<<HH / 64, 128>>>(fw, fb, out);         // launch 8
}

// round 9
// speedup vs baseline: 1.9137x; 1.1430x over previous
#include <cuda_runtime.h>
#include <cuda_bf16.h>

// Problem constants
#define BB   64
#define SS   1024
#define II   512
#define HH   512
#define NG3  1536          // 3*H
#define NWORK 96           // 3 classes x 32 working CTAs
#define NGRID 192          // padded grid (dummies exit immediately)
#define BWORDS 24576       // B_perm words (96 KB)
#define SCAN_SMEM 131072   // request > 113KB -> 1 CTA/SM guaranteed

// ---------------- static device scratch --------------------------------------
__device__ float g_xs1[(long)SS * BB * NG3];     // layer-1 input projections
__device__ float g_h1perm[4][BB * HH];           // tf32 h1 ring (fragment-perm layout)
__device__ float g_h2perm[2][BB * HH];           // tf32 h2 pingpong (perm layout)
__device__ float g_xg2r[4][BB * NG3];            // layer-2 input projection ring
__device__ float g_gb1[BB * NG3];
__device__ float g_gb2[BB * NG3];
__device__ float g_h1b[BB * HH];
__device__ float g_fcin[BB * 2 * HH];            // [b][fwd H | bwd H]

__device__ unsigned g_flg[3][32];                // per-class per-CTA progress flags

// ---------------- helpers ----------------------------------------------------
__device__ __forceinline__ unsigned f2tf(float f) {
    unsigned u;
    asm("cvt.rna.tf32.f32 %0, %1;" : "=r"(u) : "f"(f));
    return u;
}

__device__ __forceinline__ void mma8(float c[4], const unsigned a[4], unsigned b0, unsigned b1) {
    asm volatile(
        "mma.sync.aligned.m16n8k8.row.col.f32.tf32.tf32.f32 "
        "{%0,%1,%2,%3},{%4,%5,%6,%7},{%8,%9},{%0,%1,%2,%3};"
        : "+f"(c[0]), "+f"(c[1]), "+f"(c[2]), "+f"(c[3])
        : "r"(a[0]), "r"(a[1]), "r"(a[2]), "r"(a[3]), "r"(b0), "r"(b1));
}

__device__ __forceinline__ float sigm(float v) { return 1.f / (1.f + __expf(-v)); }
__device__ __forceinline__ float tanh_fast(float v) {
    return 1.f - 2.f / (1.f + __expf(2.f * v));
}

// A-fragment permuted index for h element (b, u)
__device__ __forceinline__ int pidx(int b, int u) {
    return (((u >> 3) * 4 + (b >> 4)) * 32 + (b & 7) * 4 + (u & 3)) * 4
           + ((u >> 2) & 1) * 2 + ((b >> 3) & 1);
}

// distributed wait: all 32 flags of a class >= target (1 thread per flag)
__device__ __forceinline__ void wait_all(const unsigned* flags, unsigned target) {
    if (threadIdx.x < 32) {
        unsigned v;
        do {
            asm volatile("ld.acquire.gpu.u32 %0, [%1];"
                         : "=r"(v) : "l"(flags + threadIdx.x) : "memory");
        } while (__any_sync(0xFFFFFFFFu, v < target));
    }
    __syncthreads();
}

// publish own progress flag (release)
__device__ __forceinline__ void publish(unsigned* flag, unsigned target) {
    __syncthreads();
    if (threadIdx.x == 0) {
        __threadfence();
        asm volatile("st.release.gpu.u32 [%0], %1;" :: "l"(flag), "r"(target) : "memory");
    }
}

// ---------------- 64x64 TF32 GEMM core (non-scan kernels) --------------------
__device__ __forceinline__ void gemm_core(const float* __restrict__ A, long lda,
                                          const float* __restrict__ B512, int K,
                                          const float* __restrict__ bias,
                                          float* __restrict__ C, int ldc)
{
    __shared__ unsigned As[64][33];
    __shared__ unsigned Bs[32][65];

    const int tid  = threadIdx.x;
    const int lane = tid & 31;
    const int warp = tid >> 5;
    const int wm = warp >> 1, wn = warp & 1;
    const int g = lane >> 2, t = lane & 3;

    float acc[2][4][4];
#pragma unroll
    for (int a = 0; a < 2; a++)
#pragma unroll
        for (int b = 0; b < 4; b++)
#pragma unroll
            for (int c = 0; c < 4; c++) acc[a][b][c] = 0.f;

    float4 ra[4], rbv[4];
#pragma unroll
    for (int i = 0; i < 4; i++) {
        int f = tid + i * 128;
        ra[i]  = *(const float4*)(A + (long)(f >> 3) * lda + ((f & 7) << 2));
        rbv[i] = *(const float4*)(B512 + (long)(f >> 4) * 512 + ((f & 15) << 2));
    }

    for (int kc = 0; kc < K; kc += 32) {
#pragma unroll
        for (int i = 0; i < 4; i++) {
            int f = tid + i * 128;
            int r = f >> 3, cc = (f & 7) << 2;
            As[r][cc + 0] = f2tf(ra[i].x);
            As[r][cc + 1] = f2tf(ra[i].y);
            As[r][cc + 2] = f2tf(ra[i].z);
            As[r][cc + 3] = f2tf(ra[i].w);
            int bk = f >> 4, bc = (f & 15) << 2;
            Bs[bk][bc + 0] = f2tf(rbv[i].x);
            Bs[bk][bc + 1] = f2tf(rbv[i].y);
            Bs[bk][bc + 2] = f2tf(rbv[i].z);
            Bs[bk][bc + 3] = f2tf(rbv[i].w);
        }
        __syncthreads();

        if (kc + 32 < K) {
#pragma unroll
            for (int i = 0; i < 4; i++) {
                int f = tid + i * 128;
                ra[i]  = *(const float4*)(A + (long)(f >> 3) * lda + (kc + 32) + ((f & 7) << 2));
                rbv[i] = *(const float4*)(B512 + (long)(kc + 32 + (f >> 4)) * 512 + ((f & 15) << 2));
            }
        }

#pragma unroll
        for (int ks = 0; ks < 4; ks++) {
            int kb = ks * 8;
            unsigned afr[2][4];
#pragma unroll
            for (int mf = 0; mf < 2; mf++) {
                int rb_ = wm * 32 + mf * 16;
                afr[mf][0] = As[rb_ + g][kb + t];
                afr[mf][1] = As[rb_ + 8 + g][kb + t];
                afr[mf][2] = As[rb_ + g][kb + 4 + t];
                afr[mf][3] = As[rb_ + 8 + g][kb + 4 + t];
            }
#pragma unroll
            for (int nf = 0; nf < 4; nf++) {
                int cb = wn * 32 + nf * 8;
                unsigned b0 = Bs[kb + t][cb + g];
                unsigned b1 = Bs[kb + 4 + t][cb + g];
                mma8(acc[0][nf], afr[0], b0, b1);
                mma8(acc[1][nf], afr[1], b0, b1);
            }
        }
        __syncthreads();
    }

#pragma unroll
    for (int mf = 0; mf < 2; mf++)
#pragma unroll
        for (int nf = 0; nf < 4; nf++) {
            int row = wm * 32 + mf * 16 + g;
            int col = wn * 32 + nf * 8 + t * 2;
            float b0v = bias ? bias[col] : 0.f;
            float b1v = bias ? bias[col + 1] : 0.f;
            C[(long)row * ldc + col]           = acc[mf][nf][0] + b0v;
            C[(long)row * ldc + col + 1]       = acc[mf][nf][1] + b1v;
            C[(long)(row + 8) * ldc + col]     = acc[mf][nf][2] + b0v;
            C[(long)(row + 8) * ldc + col + 1] = acc[mf][nf][3] + b1v;
        }
}

// ---------------- kernels -----------------------------------------------------

__global__ void k_zero() {
    long n = BB * HH;
    for (long i = blockIdx.x * blockDim.x + threadIdx.x; i < n; i += (long)gridDim.x * blockDim.x) {
        g_h1perm[0][i] = 0.f;
        g_h2perm[0][i] = 0.f;
    }
    if (blockIdx.x == 0 && threadIdx.x < 96)
        g_flg[threadIdx.x >> 5][threadIdx.x & 31] = 0;
}

// xs1[s][b][n] = x[b][s][:] @ Wi[0][0][gate] + b[0][0]
__global__ __launch_bounds__(128) void k_proj(const float* __restrict__ x,
                                              const float* __restrict__ Wi,
                                              const float* __restrict__ bv)
{
    int n = blockIdx.x * 64;
    int s = blockIdx.y;
    int gate = n >> 9, cig = n & 511;
    const float* A = x + (long)s * II;
    const float* B512 = Wi + ((long)(0 * 3 + gate)) * 512 * 512 + cig;   // Wi[0][0]
    gemm_core(A, (long)SS * II, B512, 512, bv + n,
              g_xs1 + ((long)s * BB) * NG3 + n, NG3);
}

// ---------------- persistent scan kernel --------------------------------------
// 96 working CTAs (3 classes x 32), 128 threads. A-operand read DIRECTLY from
// the permuted global h arrays via LDG.128.CG (no smem staging, no cp.async,
// no per-iteration __syncthreads). B weights resident in smem. Distributed
// flag-array barriers (1 flag per CTA, direct polling).
//   A  (0-31):  Wh1 over h1(it)   -> EW L1 -> h1(it+1) ring[4]
//   B1 (32-63): Wi2 over h1(it+1) -> xg2[it] ring[4]
//   B2 (64-95): Wh2 over h2(it) + EW L2 (xg2[it]) -> h2(it+1)
__global__ void __launch_bounds__(128, 1) k_scan(const float* __restrict__ Wi,
                                                 const float* __restrict__ Wh,
                                                 const float* __restrict__ bv)
{
    extern __shared__ unsigned smemu[];
    unsigned* Bsm = smemu;               // B_perm

    const int tid  = threadIdx.x;
    const int lane = tid & 31;
    const int warp = tid >> 5;
    const int g = lane >> 2, t = lane & 3;
    const int ct = blockIdx.x;
    if (ct >= NWORK) return;             // grid padding (issue-throttle guard)
    const int cls = ct >> 5;             // 0=A, 1=B1, 2=B2
    const int ci  = ct & 31;
    const int u0  = ci * 16;

    // ---- one-time weight stage into B_perm (tf32); nf = uh*3 + gate ----
    const float* Wbase = (cls == 0) ? Wh : (cls == 1) ? (Wi + 6L * 262144)
                                                      : (Wh + 6L * 262144);
    for (int widx = tid; widx < BWORDS; widx += 128) {
        int w2 = widx & 1;
        int lane2 = (widx >> 1) & 31;
        int m = widx >> 6;               // k8*6 + nf
        int nf = m % 6, k8 = m / 6;
        int g2 = lane2 >> 2, tq2 = lane2 & 3;
        int kk = k8 * 8 + tq2 + 4 * w2;
        int gate = nf % 3, uh = nf / 3;
        int ucol = u0 + uh * 8 + g2;
        Bsm[widx] = f2tf(Wbase[(long)gate * 262144 + (long)kk * 512 + ucol]);
    }

    // layer-2 bias prefetch (b[1][0]) for B2
    const float* b2 = bv + 2 * NG3;
    float b2r[2][2], b2z[2][2], b2n[2][2];
    if (cls == 2) {
#pragma unroll
        for (int uh = 0; uh < 2; uh++)
#pragma unroll
            for (int jl = 0; jl < 2; jl++) {
                int u = u0 + uh * 8 + t * 2 + jl;
                b2r[uh][jl] = __ldg(b2 + u);
                b2z[uh][jl] = __ldg(b2 + 512 + u);
                b2n[uh][jl] = __ldg(b2 + 1024 + u);
            }
    }

    float hreg[2][2][2];                 // own h cells (layer1 for A, layer2 for B2)
#pragma unroll
    for (int a = 0; a < 2; a++)
#pragma unroll
        for (int b = 0; b < 2; b++)
#pragma unroll
            for (int c = 0; c < 2; c++) hreg[a][b][c] = 0.f;

    __syncthreads();                     // B_perm ready

    for (int it = 0; it < SS; it++) {
        // ---- top waits (overlap everything downstream) ----
        const float* hp;
        if (cls == 0) {
            wait_all(g_flg[0], (unsigned)it);                    // own class step
            if (it >= 4) wait_all(g_flg[1], (unsigned)(it - 3)); // h1 ring slack
            hp = g_h1perm[it & 3];
        } else if (cls == 1) {
            wait_all(g_flg[0], (unsigned)(it + 1));              // h1(it+1) ready
            if (it >= 4) wait_all(g_flg[2], (unsigned)(it - 3)); // xg2 ring slack
            hp = g_h1perm[(it + 1) & 3];
        } else {
            wait_all(g_flg[1], (unsigned)(it + 1));              // xg2[it] ready
            wait_all(g_flg[2], (unsigned)it);                    // own class step
            hp = g_h2perm[it & 1];
        }

        // EW operand prefetch (long-latency, independent of GEMM)
        float pf_x[2][2][2][3];
        if (cls == 0) {
#pragma unroll
            for (int j2 = 0; j2 < 2; j2++) {
                int b = warp * 16 + g + 8 * j2;
                const float* xs = g_xs1 + ((long)it * BB + b) * NG3;
#pragma unroll
                for (int uh = 0; uh < 2; uh++)
#pragma unroll
                    for (int jl = 0; jl < 2; jl++) {
                        int u = u0 + uh * 8 + t * 2 + jl;
                        pf_x[j2][uh][jl][0] = __ldcg(xs + u);
                        pf_x[j2][uh][jl][1] = __ldcg(xs + 512 + u);
                        pf_x[j2][uh][jl][2] = __ldcg(xs + 1024 + u);
                    }
            }
        } else if (cls == 2) {
            const float* xg = g_xg2r[it & 3];
#pragma unroll
            for (int j2 = 0; j2 < 2; j2++) {
                int b = warp * 16 + g + 8 * j2;
#pragma unroll
                for (int uh = 0; uh < 2; uh++)
#pragma unroll
                    for (int jl = 0; jl < 2; jl++) {
                        int u = u0 + uh * 8 + t * 2 + jl;
                        pf_x[j2][uh][jl][0] = __ldcg(xg + b * NG3 + u);
                        pf_x[j2][uh][jl][1] = __ldcg(xg + b * NG3 + 512 + u);
                        pf_x[j2][uh][jl][2] = __ldcg(xg + b * NG3 + 1024 + u);
                    }
            }
        }

        // ---- GEMM: A-fragments streamed from L2, 8-deep rolling prefetch ----
        const uint4* gA = (const uint4*)hp + warp * 32 + lane;
        float acc[6][4];
#pragma unroll
        for (int nf = 0; nf < 6; nf++)
#pragma unroll
            for (int c = 0; c < 4; c++) acc[nf][c] = 0.f;

        uint4 areg[8];
#pragma unroll
        for (int j = 0; j < 8; j++) areg[j] = __ldcg(gA + j * 128);

#pragma unroll 8
        for (int k8 = 0; k8 < 64; k8++) {
            unsigned a[4] = {areg[k8 & 7].x, areg[k8 & 7].y,
                             areg[k8 & 7].z, areg[k8 & 7].w};
            if (k8 + 8 < 64) areg[k8 & 7] = __ldcg(gA + (k8 + 8) * 128);
            const unsigned* Bp = Bsm + k8 * 384 + lane * 2;
#pragma unroll
            for (int nf = 0; nf < 6; nf++) {
                uint2 bb = *(const uint2*)(Bp + nf * 64);
                mma8(acc[nf], a, bb.x, bb.y);
            }
        }

        // ---- class-specific epilogue ----
        if (cls == 0) {
            float* hout = g_h1perm[(it + 1) & 3];
#pragma unroll
            for (int j2 = 0; j2 < 2; j2++) {
                int b = warp * 16 + g + 8 * j2;
#pragma unroll
                for (int uh = 0; uh < 2; uh++)
#pragma unroll
                    for (int jl = 0; jl < 2; jl++) {
                        int u = u0 + uh * 8 + t * 2 + jl;
                        int c = j2 * 2 + jl;
                        float r  = sigm(pf_x[j2][uh][jl][0] + acc[uh * 3 + 0][c]);
                        float z  = sigm(pf_x[j2][uh][jl][1] + acc[uh * 3 + 1][c]);
                        float nn = tanh_fast(pf_x[j2][uh][jl][2] + r * acc[uh * 3 + 2][c]);
                        float v  = (1.f - z) * nn + z * hreg[j2][uh][jl];
                        hreg[j2][uh][jl] = v;
                        __stcg(&hout[pidx(b, u)], __uint_as_float(f2tf(v)));
                    }
            }
            publish(&g_flg[0][ci], (unsigned)(it + 1));
        } else if (cls == 1) {
            float* xg = g_xg2r[it & 3];
#pragma unroll
            for (int uh = 0; uh < 2; uh++)
#pragma unroll
                for (int gate = 0; gate < 3; gate++)
#pragma unroll
                    for (int j2 = 0; j2 < 2; j2++) {
                        int b = warp * 16 + g + 8 * j2;
                        float2 val = make_float2(acc[uh * 3 + gate][j2 * 2],
                                                 acc[uh * 3 + gate][j2 * 2 + 1]);
                        __stcg((float2*)(xg + b * NG3 + gate * 512 + u0 + uh * 8 + t * 2), val);
                    }
            publish(&g_flg[1][ci], (unsigned)(it + 1));
        } else {
            float* hout = g_h2perm[(it + 1) & 1];
#pragma unroll
            for (int j2 = 0; j2 < 2; j2++) {
                int b = warp * 16 + g + 8 * j2;
#pragma unroll
                for (int uh = 0; uh < 2; uh++)
#pragma unroll
                    for (int jl = 0; jl < 2; jl++) {
                        int u = u0 + uh * 8 + t * 2 + jl;
                        int c = j2 * 2 + jl;
                        float xr = pf_x[j2][uh][jl][0] + b2r[uh][jl];
                        float xz = pf_x[j2][uh][jl][1] + b2z[uh][jl];
                        float xn = pf_x[j2][uh][jl][2] + b2n[uh][jl];
                        float r2 = sigm(xr + acc[uh * 3 + 0][c]);
                        float z2 = sigm(xz + acc[uh * 3 + 1][c]);
                        float n2 = tanh_fast(xn + r2 * acc[uh * 3 + 2][c]);
                        float v  = (1.f - z2) * n2 + z2 * hreg[j2][uh][jl];
                        hreg[j2][uh][jl] = v;
                        __stcg(&hout[pidx(b, u)], __uint_as_float(f2tf(v)));
                        if (it == SS - 1) __stcg(&g_fcin[b * (2 * HH) + u], v);
                    }
            }
            publish(&g_flg[2][ci], (unsigned)(it + 1));
        }
    }
}

// backward step 1 projection: x[:,1023,:] @ Wi[0][1] + b[0][1]
__global__ __launch_bounds__(128) void k_gb1(const float* __restrict__ x,
                                             const float* __restrict__ Wi,
                                             const float* __restrict__ bv)
{
    int n = blockIdx.x * 64;
    int gate = n >> 9, cig = n & 511;
    const float* A = x + (long)(SS - 1) * II;
    const float* B512 = Wi + ((long)(1 * 3 + gate)) * 512 * 512 + cig;   // Wi[0][1]
    gemm_core(A, (long)SS * II, B512, 512, bv + 1 * NG3 + n, g_gb1 + n, NG3);
}

__global__ void k_ewb1()
{
    int b = blockIdx.x, u = threadIdx.x;
    float z  = sigm(g_gb1[b * NG3 + 512 + u]);
    float nn = tanh_fast(g_gb1[b * NG3 + 1024 + u]);
    g_h1b[b * HH + u] = (1.f - z) * nn;
}

// backward step 2 projection: h1b @ Wi[1][1] + b[1][1]
__global__ __launch_bounds__(128) void k_gb2(const float* __restrict__ Wi,
                                             const float* __restrict__ bv)
{
    int n = blockIdx.x * 64;
    int gate = n >> 9, cig = n & 511;
    const float* B512 = Wi + ((long)(3 * 3 + gate)) * 512 * 512 + cig;   // Wi[1][1]
    gemm_core(g_h1b, HH, B512, 512, bv + 3 * NG3 + n, g_gb2 + n, NG3);
}

__global__ void k_ewb2()
{
    int b = blockIdx.x, u = threadIdx.x;
    float z  = sigm(g_gb2[b * NG3 + 512 + u]);
    float nn = tanh_fast(g_gb2[b * NG3 + 1024 + u]);
    g_fcin[b * (2 * HH) + HH + u] = (1.f - z) * nn;
}

// final FC: out[64,512] = fcin[64,1024] @ fc_w + fc_b
__global__ __launch_bounds__(128) void k_fc(const float* __restrict__ fw,
                                            const float* __restrict__ fb,
                                            float* __restrict__ out)
{
    int n = blockIdx.x * 64;
    gemm_core(g_fcin, 2 * HH, fw + n, 2 * HH, fb + n, out + n, HH);
}

// ---------------- launch ------------------------------------------------------
extern "C" void kernel_launch(void* const* d_in, const int* in_sizes, int n_in,
                              void* d_out, int out_size)
{
    const float* x  = (const float*)d_in[0];
    const float* Wi = (const float*)d_in[1];
    const float* Wh = (const float*)d_in[2];
    const float* bv = (const float*)d_in[3];
    const float* fw = (const float*)d_in[4];
    const float* fb = (const float*)d_in[5];
    float* out = (float*)d_out;

    cudaFuncSetAttribute(k_scan, cudaFuncAttributeMaxDynamicSharedMemorySize, SCAN_SMEM);

    k_zero<<<64, 256>>>();                       // launch 1

    dim3 gp(NG3 / 64, SS);
    k_proj<<<gp, 128>>>(x, Wi, bv);              // launch 2

    // backward direction pieces independent of the scan
    k_gb1<<<NG3 / 64, 128>>>(x, Wi, bv);         // launch 3
    k_ewb1<<<BB, HH>>>();                        // launch 4
    k_gb2<<<NG3 / 64, 128>>>(Wi, bv);            // launch 5

    // forward scan: launch 6
    k_scan<<<NGRID, 128, SCAN_SMEM>>>(Wi, Wh, bv);

    k_ewb2<<<BB, HH>>>();                        // launch 7
    k_fc<<<HH / 64, 128>>>(fw, fb, out);         // launch 8
}

// round 10
// speedup vs baseline: 2.0421x; 1.0671x over previous
#include <cuda_runtime.h>
#include <cuda_fp16.h>
#include <cuda_bf16.h>

// Problem constants
#define BB   64
#define SS   1024
#define II   512
#define HH   512
#define NG3  1536          // 3*H
#define NWORK 96           // 3 classes x 32 working CTAs
#define NGRID 192          // padded grid (dummies exit immediately)
#define BWORDS 12288       // B_perm fp16x2 words (48 KB)
#define SCAN_SMEM 131072   // request > 113KB -> 1 CTA/SM guaranteed

// ---------------- static device scratch --------------------------------------
__device__ float g_xs1[(long)SS * BB * NG3];     // layer-1 input projections
__device__ unsigned g_h1p16[4][BB * HH / 2];     // fp16x2 h1 ring (fragment-perm)
__device__ unsigned g_h2p16[2][BB * HH / 2];     // fp16x2 h2 pingpong (perm)
__device__ float g_xg2r[4][BB * NG3];            // layer-2 input projection ring
__device__ float g_gb1[BB * NG3];
__device__ float g_gb2[BB * NG3];
__device__ float g_h1b[BB * HH];
__device__ float g_fcin[BB * 2 * HH];            // [b][fwd H | bwd H]

__device__ unsigned g_flg[3][32];                // per-class per-CTA progress flags

// ---------------- helpers ----------------------------------------------------
__device__ __forceinline__ unsigned f2tf(float f) {
    unsigned u;
    asm("cvt.rna.tf32.f32 %0, %1;" : "=r"(u) : "f"(f));
    return u;
}

__device__ __forceinline__ unsigned packh2(float lo, float hi) {
    __half2 h = __floats2half2_rn(lo, hi);
    return *(unsigned*)&h;
}

// fp16 MMA: D[16x8] += A[16x16] * B[16x8], fp32 accum
__device__ __forceinline__ void mmah(float c[4], const unsigned a[4], unsigned b0, unsigned b1) {
    asm volatile(
        "mma.sync.aligned.m16n8k16.row.col.f32.f16.f16.f32 "
        "{%0,%1,%2,%3},{%4,%5,%6,%7},{%8,%9},{%0,%1,%2,%3};"
        : "+f"(c[0]), "+f"(c[1]), "+f"(c[2]), "+f"(c[3])
        : "r"(a[0]), "r"(a[1]), "r"(a[2]), "r"(a[3]), "r"(b0), "r"(b1));
}

// tf32 MMA (non-scan kernels)
__device__ __forceinline__ void mma8(float c[4], const unsigned a[4], unsigned b0, unsigned b1) {
    asm volatile(
        "mma.sync.aligned.m16n8k8.row.col.f32.tf32.tf32.f32 "
        "{%0,%1,%2,%3},{%4,%5,%6,%7},{%8,%9},{%0,%1,%2,%3};"
        : "+f"(c[0]), "+f"(c[1]), "+f"(c[2]), "+f"(c[3])
        : "r"(a[0]), "r"(a[1]), "r"(a[2]), "r"(a[3]), "r"(b0), "r"(b1));
}

__device__ __forceinline__ float sigm(float v) { return 1.f / (1.f + __expf(-v)); }
__device__ __forceinline__ float tanh_fast(float v) {
    return 1.f - 2.f / (1.f + __expf(2.f * v));
}

// distributed wait: all 32 flags of a class >= target (1 thread per flag)
__device__ __forceinline__ void wait_all(const unsigned* flags, unsigned target) {
    if (threadIdx.x < 32) {
        unsigned v;
        do {
            asm volatile("ld.acquire.gpu.u32 %0, [%1];"
                         : "=r"(v) : "l"(flags + threadIdx.x) : "memory");
        } while (__any_sync(0xFFFFFFFFu, v < target));
    }
    __syncthreads();
}

// publish own progress flag (release)
__device__ __forceinline__ void publish(unsigned* flag, unsigned target) {
    __syncthreads();
    if (threadIdx.x == 0) {
        __threadfence();
        asm volatile("st.release.gpu.u32 [%0], %1;" :: "l"(flag), "r"(target) : "memory");
    }
}

// ---------------- 64x64 TF32 GEMM core (non-scan kernels) --------------------
__device__ __forceinline__ void gemm_core(const float* __restrict__ A, long lda,
                                          const float* __restrict__ B512, int K,
                                          const float* __restrict__ bias,
                                          float* __restrict__ C, int ldc)
{
    __shared__ unsigned As[64][33];
    __shared__ unsigned Bs[32][65];

    const int tid  = threadIdx.x;
    const int lane = tid & 31;
    const int warp = tid >> 5;
    const int wm = warp >> 1, wn = warp & 1;
    const int g = lane >> 2, t = lane & 3;

    float acc[2][4][4];
#pragma unroll
    for (int a = 0; a < 2; a++)
#pragma unroll
        for (int b = 0; b < 4; b++)
#pragma unroll
            for (int c = 0; c < 4; c++) acc[a][b][c] = 0.f;

    float4 ra[4], rbv[4];
#pragma unroll
    for (int i = 0; i < 4; i++) {
        int f = tid + i * 128;
        ra[i]  = *(const float4*)(A + (long)(f >> 3) * lda + ((f & 7) << 2));
        rbv[i] = *(const float4*)(B512 + (long)(f >> 4) * 512 + ((f & 15) << 2));
    }

    for (int kc = 0; kc < K; kc += 32) {
#pragma unroll
        for (int i = 0; i < 4; i++) {
            int f = tid + i * 128;
            int r = f >> 3, cc = (f & 7) << 2;
            As[r][cc + 0] = f2tf(ra[i].x);
            As[r][cc + 1] = f2tf(ra[i].y);
            As[r][cc + 2] = f2tf(ra[i].z);
            As[r][cc + 3] = f2tf(ra[i].w);
            int bk = f >> 4, bc = (f & 15) << 2;
            Bs[bk][bc + 0] = f2tf(rbv[i].x);
            Bs[bk][bc + 1] = f2tf(rbv[i].y);
            Bs[bk][bc + 2] = f2tf(rbv[i].z);
            Bs[bk][bc + 3] = f2tf(rbv[i].w);
        }
        __syncthreads();

        if (kc + 32 < K) {
#pragma unroll
            for (int i = 0; i < 4; i++) {
                int f = tid + i * 128;
                ra[i]  = *(const float4*)(A + (long)(f >> 3) * lda + (kc + 32) + ((f & 7) << 2));
                rbv[i] = *(const float4*)(B512 + (long)(kc + 32 + (f >> 4)) * 512 + ((f & 15) << 2));
            }
        }

#pragma unroll
        for (int ks = 0; ks < 4; ks++) {
            int kb = ks * 8;
            unsigned afr[2][4];
#pragma unroll
            for (int mf = 0; mf < 2; mf++) {
                int rb_ = wm * 32 + mf * 16;
                afr[mf][0] = As[rb_ + g][kb + t];
                afr[mf][1] = As[rb_ + 8 + g][kb + t];
                afr[mf][2] = As[rb_ + g][kb + 4 + t];
                afr[mf][3] = As[rb_ + 8 + g][kb + 4 + t];
            }
#pragma unroll
            for (int nf = 0; nf < 4; nf++) {
                int cb = wn * 32 + nf * 8;
                unsigned b0 = Bs[kb + t][cb + g];
                unsigned b1 = Bs[kb + 4 + t][cb + g];
                mma8(acc[0][nf], afr[0], b0, b1);
                mma8(acc[1][nf], afr[1], b0, b1);
            }
        }
        __syncthreads();
    }

#pragma unroll
    for (int mf = 0; mf < 2; mf++)
#pragma unroll
        for (int nf = 0; nf < 4; nf++) {
            int row = wm * 32 + mf * 16 + g;
            int col = wn * 32 + nf * 8 + t * 2;
            float b0v = bias ? bias[col] : 0.f;
            float b1v = bias ? bias[col + 1] : 0.f;
            C[(long)row * ldc + col]           = acc[mf][nf][0] + b0v;
            C[(long)row * ldc + col + 1]       = acc[mf][nf][1] + b1v;
            C[(long)(row + 8) * ldc + col]     = acc[mf][nf][2] + b0v;
            C[(long)(row + 8) * ldc + col + 1] = acc[mf][nf][3] + b1v;
        }
}

// ---------------- kernels -----------------------------------------------------

__global__ void k_zero() {
    long n = BB * HH / 2;
    for (long i = blockIdx.x * blockDim.x + threadIdx.x; i < n; i += (long)gridDim.x * blockDim.x) {
        g_h1p16[0][i] = 0u;
        g_h2p16[0][i] = 0u;
    }
    if (blockIdx.x == 0 && threadIdx.x < 96)
        g_flg[threadIdx.x >> 5][threadIdx.x & 31] = 0;
}

// xs1[s][b][n] = x[b][s][:] @ Wi[0][0][gate] + b[0][0]
__global__ __launch_bounds__(128) void k_proj(const float* __restrict__ x,
                                              const float* __restrict__ Wi,
                                              const float* __restrict__ bv)
{
    int n = blockIdx.x * 64;
    int s = blockIdx.y;
    int gate = n >> 9, cig = n & 511;
    const float* A = x + (long)s * II;
    const float* B512 = Wi + ((long)(0 * 3 + gate)) * 512 * 512 + cig;   // Wi[0][0]
    gemm_core(A, (long)SS * II, B512, 512, bv + n,
              g_xs1 + ((long)s * BB) * NG3 + n, NG3);
}

// ---------------- persistent scan kernel (FP16 MMA) ----------------------------
// 96 working CTAs (3 classes x 32), 128 threads. A-fragments (h, fp16x2, perm
// layout) streamed straight from L2 via LDG.128.CG; B weights (fp16x2) resident
// in smem. m16n8k16.f16 with fp32 accumulators. Distributed flag barriers.
//   A  (0-31):  Wh1 over h1(it)   -> EW L1 -> h1(it+1) ring[4]
//   B1 (32-63): Wi2 over h1(it+1) -> xg2[it] ring[4]
//   B2 (64-95): Wh2 over h2(it) + EW L2 (xg2[it]) -> h2(it+1)
__global__ void __launch_bounds__(128, 1) k_scan(const float* __restrict__ Wi,
                                                 const float* __restrict__ Wh,
                                                 const float* __restrict__ bv)
{
    extern __shared__ unsigned smemu[];
    unsigned* Bsm = smemu;               // B_perm fp16x2

    const int tid  = threadIdx.x;
    const int lane = tid & 31;
    const int warp = tid >> 5;
    const int g = lane >> 2, t = lane & 3;
    const int ct = blockIdx.x;
    if (ct >= NWORK) return;             // grid padding
    const int cls = ct >> 5;             // 0=A, 1=B1, 2=B2
    const int ci  = ct & 31;
    const int u0  = ci * 16;

    // ---- one-time weight stage into B_perm (fp16x2); nf = uh*3 + gate ----
    // layout: ((c*6 + nf)*32 + lane)*2 + reg ; reg0 = k{c*16+t*2, +1}, reg1 = +8
    const float* Wbase = (cls == 0) ? Wh : (cls == 1) ? (Wi + 6L * 262144)
                                                      : (Wh + 6L * 262144);
    for (int widx = tid; widx < BWORDS; widx += 128) {
        int reg = widx & 1;
        int lane2 = (widx >> 1) & 31;
        int m = widx >> 6;               // c*6 + nf
        int nf = m % 6, c = m / 6;
        int g2 = lane2 >> 2, t2 = lane2 & 3;
        int kk = c * 16 + reg * 8 + t2 * 2;
        int gate = nf % 3, uh = nf / 3;
        int col = u0 + uh * 8 + g2;
        const float* Wg = Wbase + (long)gate * 262144;
        Bsm[widx] = packh2(Wg[(long)kk * 512 + col], Wg[(long)(kk + 1) * 512 + col]);
    }

    // layer-2 bias prefetch (b[1][0]) for B2
    const float* b2 = bv + 2 * NG3;
    float b2r[2][2], b2z[2][2], b2n[2][2];
    if (cls == 2) {
#pragma unroll
        for (int uh = 0; uh < 2; uh++)
#pragma unroll
            for (int jl = 0; jl < 2; jl++) {
                int u = u0 + uh * 8 + t * 2 + jl;
                b2r[uh][jl] = __ldg(b2 + u);
                b2z[uh][jl] = __ldg(b2 + 512 + u);
                b2n[uh][jl] = __ldg(b2 + 1024 + u);
            }
    }

    float hreg[2][2][2];                 // own h cells, fp32 (A: layer1, B2: layer2)
#pragma unroll
    for (int a = 0; a < 2; a++)
#pragma unroll
        for (int b = 0; b < 2; b++)
#pragma unroll
            for (int c = 0; c < 2; c++) hreg[a][b][c] = 0.f;

    __syncthreads();                     // B_perm ready

    for (int it = 0; it < SS; it++) {
        // ---- top waits ----
        const unsigned* hp;
        if (cls == 0) {
            wait_all(g_flg[0], (unsigned)it);
            if (it >= 4) wait_all(g_flg[1], (unsigned)(it - 3));
            hp = g_h1p16[it & 3];
        } else if (cls == 1) {
            wait_all(g_flg[0], (unsigned)(it + 1));
            if (it >= 4) wait_all(g_flg[2], (unsigned)(it - 3));
            hp = g_h1p16[(it + 1) & 3];
        } else {
            wait_all(g_flg[1], (unsigned)(it + 1));
            wait_all(g_flg[2], (unsigned)it);
            hp = g_h2p16[it & 1];
        }

        // EW operand prefetch (independent of GEMM)
        float pf_x[2][2][2][3];
        if (cls == 0) {
#pragma unroll
            for (int j2 = 0; j2 < 2; j2++) {
                int b = warp * 16 + g + 8 * j2;
                const float* xs = g_xs1 + ((long)it * BB + b) * NG3;
#pragma unroll
                for (int uh = 0; uh < 2; uh++)
#pragma unroll
                    for (int jl = 0; jl < 2; jl++) {
                        int u = u0 + uh * 8 + t * 2 + jl;
                        pf_x[j2][uh][jl][0] = __ldcg(xs + u);
                        pf_x[j2][uh][jl][1] = __ldcg(xs + 512 + u);
                        pf_x[j2][uh][jl][2] = __ldcg(xs + 1024 + u);
                    }
            }
        } else if (cls == 2) {
            const float* xg = g_xg2r[it & 3];
#pragma unroll
            for (int j2 = 0; j2 < 2; j2++) {
                int b = warp * 16 + g + 8 * j2;
#pragma unroll
                for (int uh = 0; uh < 2; uh++)
#pragma unroll
                    for (int jl = 0; jl < 2; jl++) {
                        int u = u0 + uh * 8 + t * 2 + jl;
                        pf_x[j2][uh][jl][0] = __ldcg(xg + b * NG3 + u);
                        pf_x[j2][uh][jl][1] = __ldcg(xg + b * NG3 + 512 + u);
                        pf_x[j2][uh][jl][2] = __ldcg(xg + b * NG3 + 1024 + u);
                    }
            }
        }

        // ---- GEMM: 32 k16-chunks, A from L2, rolling 8-deep prefetch ----
        // A-frag uint4 index for chunk c: (c*4 + warp)*32 + lane
        const uint4* gA = (const uint4*)hp + warp * 32 + lane;
        float acc[6][4];
#pragma unroll
        for (int nf = 0; nf < 6; nf++)
#pragma unroll
            for (int c = 0; c < 4; c++) acc[nf][c] = 0.f;

        uint4 areg[8];
#pragma unroll
        for (int j = 0; j < 8; j++) areg[j] = __ldcg(gA + j * 128);

#pragma unroll 8
        for (int c = 0; c < 32; c++) {
            unsigned a[4] = {areg[c & 7].x, areg[c & 7].y,
                             areg[c & 7].z, areg[c & 7].w};
            if (c + 8 < 32) areg[c & 7] = __ldcg(gA + (c + 8) * 128);
            const unsigned* Bp = Bsm + c * 384 + lane * 2;
#pragma unroll
            for (int nf = 0; nf < 6; nf++) {
                uint2 bb = *(const uint2*)(Bp + nf * 64);
                mmah(acc[nf], a, bb.x, bb.y);
            }
        }

        // ---- class-specific epilogue ----
        if (cls == 0) {
            unsigned* hout = g_h1p16[(it + 1) & 3];
            unsigned base = ((unsigned)(ci * 4 + warp) * 32 + lane) * 4;
#pragma unroll
            for (int j2 = 0; j2 < 2; j2++) {
#pragma unroll
                for (int uh = 0; uh < 2; uh++) {
                    float v2[2];
#pragma unroll
                    for (int jl = 0; jl < 2; jl++) {
                        int c = j2 * 2 + jl;
                        float r  = sigm(pf_x[j2][uh][jl][0] + acc[uh * 3 + 0][c]);
                        float z  = sigm(pf_x[j2][uh][jl][1] + acc[uh * 3 + 1][c]);
                        float nn = tanh_fast(pf_x[j2][uh][jl][2] + r * acc[uh * 3 + 2][c]);
                        float v  = (1.f - z) * nn + z * hreg[j2][uh][jl];
                        hreg[j2][uh][jl] = v;
                        v2[jl] = v;
                    }
                    __stcg(&hout[base + j2 + 2 * uh], packh2(v2[0], v2[1]));
                }
            }
            publish(&g_flg[0][ci], (unsigned)(it + 1));
        } else if (cls == 1) {
            float* xg = g_xg2r[it & 3];
#pragma unroll
            for (int uh = 0; uh < 2; uh++)
#pragma unroll
                for (int gate = 0; gate < 3; gate++)
#pragma unroll
                    for (int j2 = 0; j2 < 2; j2++) {
                        int b = warp * 16 + g + 8 * j2;
                        float2 val = make_float2(acc[uh * 3 + gate][j2 * 2],
                                                 acc[uh * 3 + gate][j2 * 2 + 1]);
                        __stcg((float2*)(xg + b * NG3 + gate * 512 + u0 + uh * 8 + t * 2), val);
                    }
            publish(&g_flg[1][ci], (unsigned)(it + 1));
        } else {
            unsigned* hout = g_h2p16[(it + 1) & 1];
            unsigned base = ((unsigned)(ci * 4 + warp) * 32 + lane) * 4;
#pragma unroll
            for (int j2 = 0; j2 < 2; j2++) {
                int b = warp * 16 + g + 8 * j2;
#pragma unroll
                for (int uh = 0; uh < 2; uh++) {
                    float v2[2];
#pragma unroll
                    for (int jl = 0; jl < 2; jl++) {
                        int u = u0 + uh * 8 + t * 2 + jl;
                        int c = j2 * 2 + jl;
                        float xr = pf_x[j2][uh][jl][0] + b2r[uh][jl];
                        float xz = pf_x[j2][uh][jl][1] + b2z[uh][jl];
                        float xn = pf_x[j2][uh][jl][2] + b2n[uh][jl];
                        float r2 = sigm(xr + acc[uh * 3 + 0][c]);
                        float z2 = sigm(xz + acc[uh * 3 + 1][c]);
                        float n2 = tanh_fast(xn + r2 * acc[uh * 3 + 2][c]);
                        float v  = (1.f - z2) * n2 + z2 * hreg[j2][uh][jl];
                        hreg[j2][uh][jl] = v;
                        v2[jl] = v;
                        if (it == SS - 1) __stcg(&g_fcin[b * (2 * HH) + u], v);
                    }
                    __stcg(&hout[base + j2 + 2 * uh], packh2(v2[0], v2[1]));
                }
            }
            publish(&g_flg[2][ci], (unsigned)(it + 1));
        }
    }
}

// backward step 1 projection: x[:,1023,:] @ Wi[0][1] + b[0][1]
__global__ __launch_bounds__(128) void k_gb1(const float* __restrict__ x,
                                             const float* __restrict__ Wi,
                                             const float* __restrict__ bv)
{
    int n = blockIdx.x * 64;
    int gate = n >> 9, cig = n & 511;
    const float* A = x + (long)(SS - 1) * II;
    const float* B512 = Wi + ((long)(1 * 3 + gate)) * 512 * 512 + cig;   // Wi[0][1]
    gemm_core(A, (long)SS * II, B512, 512, bv + 1 * NG3 + n, g_gb1 + n, NG3);
}

__global__ void k_ewb1()
{
    int b = blockIdx.x, u = threadIdx.x;
    float z  = sigm(g_gb1[b * NG3 + 512 + u]);
    float nn = tanh_fast(g_gb1[b * NG3 + 1024 + u]);
    g_h1b[b * HH + u] = (1.f - z) * nn;
}

// backward step 2 projection: h1b @ Wi[1][1] + b[1][1]
__global__ __launch_bounds__(128) void k_gb2(const float* __restrict__ Wi,
                                             const float* __restrict__ bv)
{
    int n = blockIdx.x * 64;
    int gate = n >> 9, cig = n & 511;
    const float* B512 = Wi + ((long)(3 * 3 + gate)) * 512 * 512 + cig;   // Wi[1][1]
    gemm_core(g_h1b, HH, B512, 512, bv + 3 * NG3 + n, g_gb2 + n, NG3);
}

__global__ void k_ewb2()
{
    int b = blockIdx.x, u = threadIdx.x;
    float z  = sigm(g_gb2[b * NG3 + 512 + u]);
    float nn = tanh_fast(g_gb2[b * NG3 + 1024 + u]);
    g_fcin[b * (2 * HH) + HH + u] = (1.f - z) * nn;
}

// final FC: out[64,512] = fcin[64,1024] @ fc_w + fc_b
__global__ __launch_bounds__(128) void k_fc(const float* __restrict__ fw,
                                            const float* __restrict__ fb,
                                            float* __restrict__ out)
{
    int n = blockIdx.x * 64;
    gemm_core(g_fcin, 2 * HH, fw + n, 2 * HH, fb + n, out + n, HH);
}

// ---------------- launch ------------------------------------------------------
extern "C" void kernel_launch(void* const* d_in, const int* in_sizes, int n_in,
                              void* d_out, int out_size)
{
    const float* x  = (const float*)d_in[0];
    const float* Wi = (const float*)d_in[1];
    const float* Wh = (const float*)d_in[2];
    const float* bv = (const float*)d_in[3];
    const float* fw = (const float*)d_in[4];
    const float* fb = (const float*)d_in[5];
    float* out = (float*)d_out;

    cudaFuncSetAttribute(k_scan, cudaFuncAttributeMaxDynamicSharedMemorySize, SCAN_SMEM);

    k_zero<<<64, 256>>>();                       // launch 1

    dim3 gp(NG3 / 64, SS);
    k_proj<<<gp, 128>>>(x, Wi, bv);              // launch 2

    k_gb1<<<NG3 / 64, 128>>>(x, Wi, bv);         // launch 3

    // forward scan at launch position 4 (the slot ncu has been capturing)
    k_scan<<<NGRID, 128, SCAN_SMEM>>>(Wi, Wh, bv);

    k_ewb1<<<BB, HH>>>();                        // launch 5
    k_gb2<<<NG3 / 64, 128>>>(Wi, bv);            // launch 6
    k_ewb2<<<BB, HH>>>();                        // launch 7
    k_fc<<<HH / 64, 128>>>(fw, fb, out);         // launch 8
}